// round 12
// baseline (speedup 1.0000x reference)
#include <cuda_runtime.h>
#include <math.h>
#include <stdint.h>

#define D_    512
#define HID_  2048
#define L_    4
#define V_    32000
#define B_    2
#define T_    1025
#define S_    128
#define NH_   8
#define DH_   64
#define NT_   256
#define NCH_  8
#define LR_   0.0003f
#define ASC_  0.125f

#define ND_  (NT_*D_)
#define NH1_ (NT_*HID_)
#define NQ_  (NT_*3*D_)
#define NA_  (B_*NH_*S_*S_)
#define MND_ 131072           // 256*512

// ---------------- device scratch ----------------
__device__ float g_W1[L_*D_*HID_];
__device__ float g_W2[L_*HID_*D_];
__device__ float g_b1[L_*HID_];
__device__ float g_b2[L_*D_];
__device__ float g_h[L_*ND_];
__device__ float g_hmid[L_*ND_];
__device__ float g_hfin[ND_];
__device__ float g_m[L_*ND_];
__device__ float g_qkv[L_*NQ_];
__device__ float g_att[L_*NA_];
__device__ float g_z1[L_*NH1_];
__device__ float g_gl[L_*NH1_];
__device__ float g_abuf[ND_];
__device__ float g_obuf[ND_];
__device__ float g_dh[ND_];
__device__ float g_dtH[NH1_];
__device__ float g_dob[ND_];
__device__ float g_dqkv[NQ_];
__device__ float g_ds[NA_];
__device__ float g_dlog[NT_*V_];
__device__ float g_work[8*1024*1024];     // split-K partials (32 MB)

// ---------------- fast-math helpers ----------------
__device__ __forceinline__ float ftanh_(float u) {
    u = fminf(fmaxf(u, -15.f), 15.f);
    float e = __expf(2.f * u);
    return __fdividef(e - 1.f, e + 1.f);
}
__device__ __forceinline__ float gelu_f(float x) {
    float u = 0.7978845608028654f * (x + 0.044715f * x * x * x);
    return 0.5f * x * (1.f + ftanh_(u));
}
__device__ __forceinline__ float dgelu_f(float x) {
    float x2 = x * x;
    float u = 0.7978845608028654f * (x + 0.044715f * x * x2);
    float t = ftanh_(u);
    return 0.5f * (1.f + t)
         + 0.5f * x * (1.f - t * t) * 0.7978845608028654f * (1.f + 3.f * 0.044715f * x2);
}
__device__ __forceinline__ float f2tf_f(float f) {
    uint32_t u;
    asm("cvt.rna.tf32.f32 %0, %1;" : "=r"(u) : "f"(f));
    return __uint_as_float(u);
}

// ---------------- two-level block reductions (2 syncs each) ----------------
template<int NW>
__device__ __forceinline__ float bsum(float v, volatile float* sh) {
    #pragma unroll
    for (int o = 16; o; o >>= 1) v += __shfl_down_sync(0xffffffffu, v, o);
    if ((threadIdx.x & 31) == 0) sh[threadIdx.x >> 5] = v;
    __syncthreads();
    float r = sh[0];
    #pragma unroll
    for (int k = 1; k < NW; k++) r += sh[k];
    __syncthreads();
    return r;
}
template<int NW>
__device__ __forceinline__ float bmax(float v, volatile float* sh) {
    #pragma unroll
    for (int o = 16; o; o >>= 1) v = fmaxf(v, __shfl_down_sync(0xffffffffu, v, o));
    if ((threadIdx.x & 31) == 0) sh[threadIdx.x >> 5] = v;
    __syncthreads();
    float r = sh[0];
    #pragma unroll
    for (int k = 1; k < NW; k++) r = fmaxf(r, sh[k]);
    __syncthreads();
    return r;
}

// ---------------- 128x64x16 tf32 tensor-core GEMM (2 CTAs/SM) ----------------
// batched==0, nz>1 : raw partials to work[z]
// batched==0, nz==1: epilogue modes:
//   mode 0: C = alpha*acc + bias? + beta*C
//   mode 1: C = acc + bias ; gl = gelu(C)
//   mode 2: C = acc * dgelu(zbuf)
// batched==1: gridDim.z = batch index; full K; A/C offset by z strides
#define ASTR 136
#define BSTR 72
template<int TA, int TB>
__global__ void __launch_bounds__(256) gemm64(
    int M, int N, int K, float alpha,
    const float* __restrict__ A, int lda,
    const float* __restrict__ B, int ldb,
    float beta, float* __restrict__ C, int ldc,
    const float* __restrict__ bias, float* __restrict__ work,
    int batched, size_t sAz, size_t sCz,
    const float* __restrict__ zbuf, float* __restrict__ gl, int mode)
{
    __shared__ __align__(16) float As[2][16*ASTR];
    __shared__ __align__(16) float Bs[2][16*BSTR];
    const int tid = threadIdx.x;
    const int m0 = blockIdx.y * 128, n0 = blockIdx.x * 64;
    const int z = blockIdx.z;
    const int nz = batched ? 1 : gridDim.z;
    const int kslice = batched ? K : (K / gridDim.z);
    const int kbeg = batched ? 0 : z * kslice;
    if (batched) { A += (size_t)z * sAz; C += (size_t)z * sCz; }

    const int a_r = TA ? (tid >> 4) : (tid >> 1);
    const int a_c = TA ? ((tid & 15) * 8) : ((tid & 1) * 8);
    const int b_r = TB ? (tid >> 2) : (tid >> 4);
    const int b_c = TB ? ((tid & 3) * 4) : ((tid & 15) * 4);

    float4 pa0, pa1, pb0;

    auto ldg = [&](int kk) {
        const float* pa = TA ? (A + (size_t)(kk + a_r) * lda + m0 + a_c)
                             : (A + (size_t)(m0 + a_r) * lda + kk + a_c);
        pa0 = *(const float4*)pa; pa1 = *(const float4*)(pa + 4);
        const float* pb = TB ? (B + (size_t)(n0 + b_r) * ldb + kk + b_c)
                             : (B + (size_t)(kk + b_r) * ldb + n0 + b_c);
        pb0 = *(const float4*)pb;
    };
    auto sts = [&](int buf) {
        float va[8] = {pa0.x,pa0.y,pa0.z,pa0.w,pa1.x,pa1.y,pa1.z,pa1.w};
        float vb[4] = {pb0.x,pb0.y,pb0.z,pb0.w};
        #pragma unroll
        for (int i = 0; i < 8; i++) va[i] = f2tf_f(va[i]);
        #pragma unroll
        for (int i = 0; i < 4; i++) vb[i] = f2tf_f(vb[i]);
        if (!TA) {
            #pragma unroll
            for (int i = 0; i < 8; i++) As[buf][(a_c + i) * ASTR + a_r] = va[i];
        } else {
            float4 w0 = {va[0],va[1],va[2],va[3]}, w1 = {va[4],va[5],va[6],va[7]};
            *(float4*)&As[buf][a_r * ASTR + a_c]     = w0;
            *(float4*)&As[buf][a_r * ASTR + a_c + 4] = w1;
        }
        if (!TB) {
            float4 w0 = {vb[0],vb[1],vb[2],vb[3]};
            *(float4*)&Bs[buf][b_r * BSTR + b_c] = w0;
        } else {
            #pragma unroll
            for (int i = 0; i < 4; i++) Bs[buf][(b_c + i) * BSTR + b_r] = vb[i];
        }
    };

    const int warp = tid >> 5, lane = tid & 31;
    const int mb = (warp >> 1) * 32;
    const int nb = (warp & 1) * 32;
    const int fr = lane >> 2, fq = lane & 3;

    float acc[2][4][4];
    #pragma unroll
    for (int i = 0; i < 2; i++)
        #pragma unroll
        for (int j = 0; j < 4; j++)
            #pragma unroll
            for (int e = 0; e < 4; e++) acc[i][j][e] = 0.f;

    ldg(kbeg); sts(0); __syncthreads();
    const int KT = kslice >> 4;
    for (int kt = 0; kt < KT; kt++) {
        int buf = kt & 1;
        if (kt + 1 < KT) ldg(kbeg + (kt + 1) * 16);
        #pragma unroll
        for (int ks = 0; ks < 16; ks += 8) {
            uint32_t af[2][4], bf[4][2];
            #pragma unroll
            for (int i = 0; i < 2; i++) {
                const float* ap = &As[buf][(ks + fq) * ASTR + mb + 16*i + fr];
                af[i][0] = __float_as_uint(ap[0]);
                af[i][1] = __float_as_uint(ap[8]);
                af[i][2] = __float_as_uint(ap[4*ASTR]);
                af[i][3] = __float_as_uint(ap[4*ASTR + 8]);
            }
            #pragma unroll
            for (int j = 0; j < 4; j++) {
                const float* bp = &Bs[buf][(ks + fq) * BSTR + nb + 8*j + fr];
                bf[j][0] = __float_as_uint(bp[0]);
                bf[j][1] = __float_as_uint(bp[4*BSTR]);
            }
            #pragma unroll
            for (int i = 0; i < 2; i++)
                #pragma unroll
                for (int j = 0; j < 4; j++)
                    asm volatile(
                        "mma.sync.aligned.m16n8k8.row.col.f32.tf32.tf32.f32 "
                        "{%0,%1,%2,%3}, {%4,%5,%6,%7}, {%8,%9}, {%0,%1,%2,%3};"
                        : "+f"(acc[i][j][0]), "+f"(acc[i][j][1]),
                          "+f"(acc[i][j][2]), "+f"(acc[i][j][3])
                        : "r"(af[i][0]), "r"(af[i][1]), "r"(af[i][2]), "r"(af[i][3]),
                          "r"(bf[j][0]), "r"(bf[j][1]));
        }
        if (kt + 1 < KT) sts(buf ^ 1);
        __syncthreads();
    }

    if (nz > 1) {
        float* W = work + (size_t)z * M * N;
        #pragma unroll
        for (int i = 0; i < 2; i++) {
            int row = m0 + mb + 16*i + fr;
            #pragma unroll
            for (int j = 0; j < 4; j++) {
                int col = n0 + nb + 8*j + 2*fq;
                float2 v0 = {acc[i][j][0], acc[i][j][1]};
                float2 v1 = {acc[i][j][2], acc[i][j][3]};
                *(float2*)&W[(size_t)row * N + col]       = v0;
                *(float2*)&W[(size_t)(row + 8) * N + col] = v1;
            }
        }
    } else {
        #pragma unroll
        for (int i = 0; i < 2; i++) {
            int row = m0 + mb + 16*i + fr;
            #pragma unroll
            for (int j = 0; j < 4; j++) {
                int col = n0 + nb + 8*j + 2*fq;
                float* c0 = C + (size_t)row * ldc + col;
                float* c1 = C + (size_t)(row + 8) * ldc + col;
                if (mode == 1) {
                    float b0 = bias[col], b1 = bias[col + 1];
                    float v0x = acc[i][j][0] + b0, v0y = acc[i][j][1] + b1;
                    float v1x = acc[i][j][2] + b0, v1y = acc[i][j][3] + b1;
                    float2 v0 = {v0x, v0y}, v1 = {v1x, v1y};
                    *(float2*)c0 = v0; *(float2*)c1 = v1;
                    float* g0 = gl + (size_t)row * ldc + col;
                    float* g1 = gl + (size_t)(row + 8) * ldc + col;
                    float2 gg0 = {gelu_f(v0x), gelu_f(v0y)};
                    float2 gg1 = {gelu_f(v1x), gelu_f(v1y)};
                    *(float2*)g0 = gg0; *(float2*)g1 = gg1;
                } else if (mode == 2) {
                    float2 za = *(const float2*)(zbuf + (size_t)row * ldc + col);
                    float2 zb = *(const float2*)(zbuf + (size_t)(row + 8) * ldc + col);
                    float2 v0 = {acc[i][j][0] * dgelu_f(za.x), acc[i][j][1] * dgelu_f(za.y)};
                    float2 v1 = {acc[i][j][2] * dgelu_f(zb.x), acc[i][j][3] * dgelu_f(zb.y)};
                    *(float2*)c0 = v0; *(float2*)c1 = v1;
                } else {
                    float v[4];
                    #pragma unroll
                    for (int e = 0; e < 4; e++) v[e] = alpha * acc[i][j][e];
                    if (bias) {
                        float b0 = bias[col], b1 = bias[col + 1];
                        v[0] += b0; v[1] += b1; v[2] += b0; v[3] += b1;
                    }
                    if (beta != 0.f) {
                        v[0] += beta * c0[0]; v[1] += beta * c0[1];
                        v[2] += beta * c1[0]; v[3] += beta * c1[1];
                    }
                    float2 v0 = {v[0], v[1]}, v1 = {v[2], v[3]};
                    *(float2*)c0 = v0; *(float2*)c1 = v1;
                }
            }
        }
    }
}

// ---------------- split-K reduce (kept for Wo/W2fwd paths without LN fusion) ----------------
__global__ void __launch_bounds__(256) reduce_k(
    const float* __restrict__ work, int nz, int MN, int N,
    float alpha, float beta, float* __restrict__ C,
    const float* __restrict__ bias,
    const float* __restrict__ zbuf, float* __restrict__ gl, int mode)
{
    int i4 = blockIdx.x * 256 + threadIdx.x;
    int MN4 = MN >> 2;
    const float4* w4 = (const float4*)work;
    float4 s = {0.f, 0.f, 0.f, 0.f};
    for (int zz = 0; zz < nz; zz++) {
        float4 p = w4[(size_t)zz * MN4 + i4];
        s.x += p.x; s.y += p.y; s.z += p.z; s.w += p.w;
    }
    s.x *= alpha; s.y *= alpha; s.z *= alpha; s.w *= alpha;
    int i = i4 << 2;
    int col = i % N;
    if (mode == 1) {
        float4 b4 = *(const float4*)&bias[col];
        s.x += b4.x; s.y += b4.y; s.z += b4.z; s.w += b4.w;
        *(float4*)&C[i] = s;
        float4 g = {gelu_f(s.x), gelu_f(s.y), gelu_f(s.z), gelu_f(s.w)};
        *(float4*)&gl[i] = g;
    } else if (mode == 2) {
        float4 z4 = *(const float4*)&zbuf[i];
        s.x *= dgelu_f(z4.x); s.y *= dgelu_f(z4.y);
        s.z *= dgelu_f(z4.z); s.w *= dgelu_f(z4.w);
        *(float4*)&C[i] = s;
    } else {
        if (bias) {
            float4 b4 = *(const float4*)&bias[col];
            s.x += b4.x; s.y += b4.y; s.z += b4.z; s.w += b4.w;
        }
        if (beta != 0.f) {
            float4 c4 = *(const float4*)&C[i];
            s.x += beta * c4.x; s.y += beta * c4.y;
            s.z += beta * c4.z; s.w += beta * c4.w;
        }
        *(float4*)&C[i] = s;
    }
}

// ---------------- reduce partials + residual + bias, then LayerNorm ----------------
__global__ void __launch_bounds__(256) reduce_ln(
    const float* __restrict__ work, int nz,
    const float* __restrict__ bias, const float* __restrict__ res,
    float* __restrict__ hout,
    const float* __restrict__ ls, const float* __restrict__ lb,
    float* __restrict__ y)
{
    __shared__ float sh[8];
    int row = blockIdx.x, tid = threadIdx.x;
    size_t base = (size_t)row * D_;
    int c = tid * 2;
    float2 v = {0.f, 0.f};
    for (int z = 0; z < nz; z++) {
        float2 p = *(const float2*)&work[(size_t)z * MND_ + base + c];
        v.x += p.x; v.y += p.y;
    }
    float2 b2 = *(const float2*)&bias[c];
    float2 r2 = *(const float2*)&res[base + c];
    v.x += b2.x + r2.x; v.y += b2.y + r2.y;
    *(float2*)&hout[base + c] = v;

    float mean = bsum<8>(v.x + v.y, sh) * (1.f / D_);
    float d0 = v.x - mean, d1 = v.y - mean;
    float var = bsum<8>(d0 * d0 + d1 * d1, sh) * (1.f / D_);
    float rstd = rsqrtf(var + 1e-5f);
    float2 s2 = *(const float2*)&ls[c];
    float2 o2 = *(const float2*)&lb[c];
    float2 out = {d0 * rstd * s2.x + o2.x, d1 * rstd * s2.y + o2.y};
    *(float2*)&y[base + c] = out;
}

// ---------------- fused embed + LN1(layer0) ----------------
__global__ void __launch_bounds__(256) embed_ln(const int* __restrict__ x,
    const float* __restrict__ emb, const float* __restrict__ pos, int off,
    float* __restrict__ h, const float* __restrict__ ls, const float* __restrict__ lb,
    float* __restrict__ y)
{
    __shared__ float sh[8];
    int row = blockIdx.x, tid = threadIdx.x;
    int b = row >> 7, s = row & 127;
    int tok = x[b * T_ + off + s];
    size_t base = (size_t)row * D_;
    int c = tid * 2;
    float2 e2 = *(const float2*)&emb[(size_t)tok * D_ + c];
    float2 p2 = *(const float2*)&pos[s * D_ + c];
    float2 v = {e2.x + p2.x, e2.y + p2.y};
    *(float2*)&h[base + c] = v;

    float mean = bsum<8>(v.x + v.y, sh) * (1.f / D_);
    float d0 = v.x - mean, d1 = v.y - mean;
    float var = bsum<8>(d0 * d0 + d1 * d1, sh) * (1.f / D_);
    float rstd = rsqrtf(var + 1e-5f);
    float2 s2 = *(const float2*)&ls[c];
    float2 o2 = *(const float2*)&lb[c];
    float2 out = {d0 * rstd * s2.x + o2.x, d1 * rstd * s2.y + o2.y};
    *(float2*)&y[base + c] = out;
}

// ---------------- LN backward with fused split-K partial sum ----------------
__global__ void __launch_bounds__(256) ln_bwd_f(const float* __restrict__ x,
    const float* __restrict__ work, int nz, const float* __restrict__ s,
    float* __restrict__ dacc, int accum)
{
    __shared__ float sh[8];
    int row = blockIdx.x, tid = threadIdx.x;
    size_t base = (size_t)row * D_;
    int c = tid * 2;
    float2 dy = {0.f, 0.f};
    for (int z = 0; z < nz; z++) {
        float2 p = *(const float2*)&work[(size_t)z * MND_ + base + c];
        dy.x += p.x; dy.y += p.y;
    }
    float2 xv = *(const float2*)&x[base + c];
    float mean = bsum<8>(xv.x + xv.y, sh) * (1.f / D_);
    float d0 = xv.x - mean, d1 = xv.y - mean;
    float var = bsum<8>(d0 * d0 + d1 * d1, sh) * (1.f / D_);
    float rstd = rsqrtf(var + 1e-5f);
    float xh0 = d0 * rstd, xh1 = d1 * rstd;
    float2 s2 = *(const float2*)&s[c];
    float g0 = s2.x * dy.x, g1 = s2.y * dy.y;
    float t1 = bsum<8>(g0 + g1, sh) * (1.f / D_);
    float t2 = bsum<8>(g0 * xh0 + g1 * xh1, sh) * (1.f / D_);
    float dx0 = rstd * (g0 - t1 - xh0 * t2);
    float dx1 = rstd * (g1 - t1 - xh1 * t2);
    float2* ar = (float2*)&dacc[base + c];
    if (accum) { float2 old = *ar; ar->x = old.x + dx0; ar->y = old.y + dx1; }
    else       { float2 nv = {dx0, dx1}; *ar = nv; }
}

// ---------------- attention forward (256 thr, 4-way parallel AV loop) ----------------
__global__ void __launch_bounds__(256) attn_fwd(const float* __restrict__ qkv,
    float* __restrict__ att, float* __restrict__ obuf)
{
    __shared__ float qs[DH_]; __shared__ float sc[S_]; __shared__ float sh[8];
    __shared__ float part[4][DH_ + 1];
    int qi = blockIdx.x, h = blockIdx.y, b = blockIdx.z, tid = threadIdx.x;
    int row = b * S_ + qi;
    if (tid < DH_) qs[tid] = qkv[(size_t)row * (3*D_) + h * DH_ + tid];
    __syncthreads();
    float sj = -1e30f;
    if (tid <= qi) {
        const float* kp = qkv + (size_t)(b * S_ + tid) * (3*D_) + D_ + h * DH_;
        float a = 0.f;
        #pragma unroll
        for (int d = 0; d < DH_; d++) a += qs[d] * kp[d];
        sj = a * ASC_;
    }
    float mx = bmax<8>(sj, sh);
    float e = (tid <= qi) ? __expf(sj - mx) : 0.f;
    float tot = bsum<8>(e, sh);
    float a = e / tot;
    size_t arow = ((size_t)(b * NH_ + h) * S_ + qi) * S_;
    if (tid < S_) { att[arow + tid] = a; sc[tid] = a; }
    __syncthreads();
    int d = tid & (DH_ - 1), p = tid >> 6;
    float acc = 0.f;
    for (int j = p; j <= qi; j += 4)
        acc += sc[j] * qkv[(size_t)(b * S_ + j) * (3*D_) + 2*D_ + h * DH_ + d];
    part[p][d] = acc;
    __syncthreads();
    if (tid < DH_)
        obuf[(size_t)row * D_ + h * DH_ + tid] =
            (part[0][tid] + part[1][tid]) + (part[2][tid] + part[3][tid]);
}

// ---------------- attention backward 1 (256 thr, fused dob partial-sum) ----------------
__global__ void __launch_bounds__(256) attn_bwd1(const float* __restrict__ qkv,
    const float* __restrict__ att, const float* __restrict__ work, int nz,
    float* __restrict__ dob, float* __restrict__ dsbuf, float* __restrict__ dqkv)
{
    __shared__ float dov[DH_]; __shared__ float sc[S_]; __shared__ float sh[8];
    __shared__ float part[4][DH_ + 1];
    int qi = blockIdx.x, h = blockIdx.y, b = blockIdx.z, tid = threadIdx.x;
    int row = b * S_ + qi;
    if (tid < DH_) {
        size_t wi = (size_t)row * D_ + h * DH_ + tid;
        float s = 0.f;
        for (int z = 0; z < nz; z++) s += work[(size_t)z * MND_ + wi];
        dov[tid] = s;
        dob[wi] = s;
    }
    __syncthreads();
    size_t arow = ((size_t)(b * NH_ + h) * S_ + qi) * S_;
    float a = (tid < S_) ? att[arow + tid] : 0.f;
    float datt = 0.f;
    if (tid <= qi) {
        const float* vp = qkv + (size_t)(b * S_ + tid) * (3*D_) + 2*D_ + h * DH_;
        #pragma unroll
        for (int d = 0; d < DH_; d++) datt += dov[d] * vp[d];
    }
    float tot = bsum<8>(a * datt, sh);
    float ds = a * (datt - tot);
    if (tid < S_) { dsbuf[arow + tid] = ds; sc[tid] = ds; }
    __syncthreads();
    int d = tid & (DH_ - 1), p = tid >> 6;
    float acc = 0.f;
    for (int j = p; j <= qi; j += 4)
        acc += sc[j] * qkv[(size_t)(b * S_ + j) * (3*D_) + D_ + h * DH_ + d];
    part[p][d] = acc;
    __syncthreads();
    if (tid < DH_)
        dqkv[(size_t)row * (3*D_) + h * DH_ + tid] =
            ((part[0][tid] + part[1][tid]) + (part[2][tid] + part[3][tid])) * ASC_;
}

// ---------------- attention backward 2 (256 thr, 4-way parallel q loop) ----------------
__global__ void __launch_bounds__(256) attn_bwd2(const float* __restrict__ qkv,
    const float* __restrict__ att, const float* __restrict__ dob,
    const float* __restrict__ dsbuf, float* __restrict__ dqkv)
{
    __shared__ float pk[4][DH_ + 1], pv[4][DH_ + 1];
    int j = blockIdx.x, h = blockIdx.y, b = blockIdx.z, tid = threadIdx.x;
    int d = tid & (DH_ - 1), p = tid >> 6;
    size_t bh = (size_t)(b * NH_ + h) * S_;
    float dk = 0.f, dv = 0.f;
    for (int q = j + p; q < S_; q += 4) {
        float ds = dsbuf[(bh + q) * S_ + j];
        float a  = att[(bh + q) * S_ + j];
        dk += ds * qkv[(size_t)(b * S_ + q) * (3*D_) + h * DH_ + d];
        dv += a  * dob[(size_t)(b * S_ + q) * D_ + h * DH_ + d];
    }
    pk[p][d] = dk; pv[p][d] = dv;
    __syncthreads();
    if (tid < DH_) {
        float dks = (pk[0][tid] + pk[1][tid]) + (pk[2][tid] + pk[3][tid]);
        float dvs = (pv[0][tid] + pv[1][tid]) + (pv[2][tid] + pv[3][tid]);
        dqkv[(size_t)(b * S_ + j) * (3*D_) + D_   + h * DH_ + tid] = dks * ASC_;
        dqkv[(size_t)(b * S_ + j) * (3*D_) + 2*D_ + h * DH_ + tid] = dvs;
    }
}

// ---------------- both bias SGD updates in one launch ----------------
__global__ void __launch_bounds__(256) bias2_sgd(const float* __restrict__ dh,
    const float* __restrict__ dtH, float* __restrict__ b2, float* __restrict__ b1)
{
    int c = blockIdx.x * 256 + threadIdx.x;
    if (c < D_) {
        float s = 0.f;
        for (int i = 0; i < NT_; i++) s += dh[(size_t)i * D_ + c];
        b2[c] -= LR_ * s;
    } else {
        int c1 = c - D_;
        float s = 0.f;
        for (int i = 0; i < NT_; i++) s += dtH[(size_t)i * HID_ + c1];
        b1[c1] -= LR_ * s;
    }
}

// ---------------- fused online softmax stats + dlogits (512 thr, float4) ----------------
__global__ void __launch_bounds__(512) smax_dlog(const float* __restrict__ out,
    const int* __restrict__ x, int off, float* __restrict__ dl)
{
    __shared__ float rm[512], rs[512];
    int i = blockIdx.x, tid = threadIdx.x;
    int b = i >> 7, s = i & 127;
    const float* lp = out + ((size_t)(b * (NCH_*S_) + off + s)) * V_;
    const float4* lp4 = (const float4*)lp;

    float m = -1e30f, sum = 0.f;
    for (int v4 = tid; v4 < V_/4; v4 += 512) {
        float4 q = lp4[v4];
        float vals[4] = {q.x, q.y, q.z, q.w};
        #pragma unroll
        for (int e = 0; e < 4; e++) {
            float v = vals[e];
            if (v > m) { sum *= __expf(m - v); m = v; }
            sum += __expf(v - m);
        }
    }
    rm[tid] = m; rs[tid] = sum; __syncthreads();
    for (int w = 256; w > 0; w >>= 1) {
        if (tid < w) {
            float m1 = rm[tid], m2 = rm[tid + w];
            float M = fmaxf(m1, m2);
            rs[tid] = rs[tid] * __expf(m1 - M) + rs[tid + w] * __expf(m2 - M);
            rm[tid] = M;
        }
        __syncthreads();
    }
    m = rm[0];
    float rinv = __fdividef(1.f, rs[0]);
    const float invNT = 1.f / NT_;
    int tgt = x[b * T_ + off + s + 1];

    float4* dl4 = (float4*)(dl + (size_t)i * V_);
    for (int v4 = tid; v4 < V_/4; v4 += 512) {
        float4 q = lp4[v4];
        int vb = v4 * 4;
        float4 p;
        p.x = (__expf(q.x - m) * rinv - (vb + 0 == tgt ? 1.f : 0.f)) * invNT;
        p.y = (__expf(q.y - m) * rinv - (vb + 1 == tgt ? 1.f : 0.f)) * invNT;
        p.z = (__expf(q.z - m) * rinv - (vb + 2 == tgt ? 1.f : 0.f)) * invNT;
        p.w = (__expf(q.w - m) * rinv - (vb + 3 == tgt ? 1.f : 0.f)) * invNT;
        dl4[v4] = p;
    }
}

// ---------------- segmented param copy (one launch) ----------------
#define NW1_ (L_*D_*HID_)
#define NW2_ (L_*HID_*D_)
#define NB1_ (L_*HID_)
#define NB2_ (L_*D_)
__global__ void __launch_bounds__(256) copy_params(
    const float* __restrict__ w1, const float* __restrict__ w2,
    const float* __restrict__ b1, const float* __restrict__ b2,
    float* __restrict__ pw1, float* __restrict__ pw2,
    float* __restrict__ pb1, float* __restrict__ pb2)
{
    int i = blockIdx.x * 256 + threadIdx.x;
    if (i < NW1_) { pw1[i] = w1[i]; }
    int j = i - NW1_;
    if (j >= 0 && j < NW2_) { pw2[j] = w2[j]; }
    int k = i - NW1_ - NW2_;
    if (k >= 0 && k < NB1_) { pb1[k] = b1[k]; }
    int l = i - NW1_ - NW2_ - NB1_;
    if (l >= 0 && l < NB2_) { pb2[l] = b2[l]; }
}

// ---------------- host ----------------
static float* P(const void* sym) { void* p = 0; cudaGetSymbolAddress(&p, sym); return (float*)p; }

static float* h_work;

static void gemmx(int TA, int TB, int M, int N, int K, int nz, float alpha,
                  const float* A, int lda, const float* B, int ldb,
                  float beta, float* C, int ldc, const float* bias,
                  const float* zbuf = 0, float* gl = 0, int mode = 0)
{
    dim3 g(N / 64, M / 128, nz);
    if (!TA && !TB)      gemm64<0,0><<<g,256>>>(M,N,K,alpha,A,lda,B,ldb,beta,C,ldc,bias,h_work,0,0,0,zbuf,gl,mode);
    else if (!TA && TB)  gemm64<0,1><<<g,256>>>(M,N,K,alpha,A,lda,B,ldb,beta,C,ldc,bias,h_work,0,0,0,zbuf,gl,mode);
    else if (TA && !TB)  gemm64<1,0><<<g,256>>>(M,N,K,alpha,A,lda,B,ldb,beta,C,ldc,bias,h_work,0,0,0,zbuf,gl,mode);
    else                 gemm64<1,1><<<g,256>>>(M,N,K,alpha,A,lda,B,ldb,beta,C,ldc,bias,h_work,0,0,0,zbuf,gl,mode);
}

extern "C" void kernel_launch(void* const* d_in, const int* in_sizes, int n_in,
                              void* d_out, int out_size)
{
    const int*   x     = (const int*)  d_in[0];
    const float* emb   = (const float*)d_in[1];
    const float* pos   = (const float*)d_in[2];
    const float* ln1s  = (const float*)d_in[3];
    const float* ln1b  = (const float*)d_in[4];
    const float* Wqkv  = (const float*)d_in[5];
    const float* bqkv  = (const float*)d_in[6];
    const float* Wo    = (const float*)d_in[7];
    const float* bo    = (const float*)d_in[8];
    const float* ln2s  = (const float*)d_in[9];
    const float* ln2b  = (const float*)d_in[10];
    const float* W1i   = (const float*)d_in[11];
    const float* b1i   = (const float*)d_in[12];
    const float* W2i   = (const float*)d_in[13];
    const float* b2i   = (const float*)d_in[14];
    const float* lnfs  = (const float*)d_in[15];
    const float* lnfb  = (const float*)d_in[16];
    const float* Whead = (const float*)d_in[17];
    const float* bhead = (const float*)d_in[18];
    float* out = (float*)d_out;

    float *pW1 = P(g_W1), *pW2 = P(g_W2), *pb1 = P(g_b1), *pb2 = P(g_b2);
    float *ph = P(g_h), *phmid = P(g_hmid), *phfin = P(g_hfin), *pm = P(g_m);
    float *pqkv = P(g_qkv), *patt = P(g_att), *pz1 = P(g_z1), *pgl = P(g_gl);
    float *pabuf = P(g_abuf), *pobuf = P(g_obuf), *pdh = P(g_dh);
    float *pdtH = P(g_dtH), *pdob = P(g_dob);
    float *pdqkv = P(g_dqkv), *pds = P(g_ds), *pdlog = P(g_dlog);
    h_work = P(g_work);

    const int copyN = NW1_ + NW2_ + NB1_ + NB2_;
    copy_params<<<(copyN + 255)/256, 256>>>(W1i, W2i, b1i, b2i, pW1, pW2, pb1, pb2);

    for (int c = 0; c < NCH_; c++) {
        const int off = c * S_;

        // ---------------- forward ----------------
        embed_ln<<<NT_, 256>>>(x, emb, pos, off, ph, ln1s, ln1b, pabuf);
        for (int l = 0; l < L_; l++) {
            float* hin = ph + (size_t)l * ND_;
            float* hmid = phmid + (size_t)l * ND_;
            float* hout = (l < L_-1) ? ph + (size_t)(l+1)*ND_ : phfin;
            const float* nls = (l < L_-1) ? ln1s + (l+1)*D_ : lnfs;
            const float* nlb = (l < L_-1) ? ln1b + (l+1)*D_ : lnfb;

            // qkv = ln1(h)@Wqkv + bqkv   (unsplit, grid 48, fused bias)
            gemmx(0,0, NT_, 3*D_, D_, 1, 1.f, pabuf, D_, Wqkv + (size_t)l*D_*3*D_, 3*D_,
                  0.f, pqkv + (size_t)l*NQ_, 3*D_, bqkv + l*3*D_);
            attn_fwd<<<dim3(S_,NH_,B_), 256>>>(pqkv + (size_t)l*NQ_, patt + (size_t)l*NA_, pobuf);
            // hmid = hin + obuf@Wo + bo ; m = ln2(hmid)   (split 16 -> reduce_ln)
            gemmx(0,0, NT_, D_, D_, 16, 1.f, pobuf, D_, Wo + (size_t)l*D_*D_, D_, 0.f, 0, 0, 0);
            reduce_ln<<<NT_, 256>>>(h_work, 16, bo + l*D_, hin, hmid,
                                    ln2s + l*D_, ln2b + l*D_, pm + (size_t)l*ND_);
            // z1 = m@W1 + b1 ; gl = gelu(z1)   (unsplit, grid 64, mode 1)
            gemmx(0,0, NT_, HID_, D_, 1, 1.f, pm + (size_t)l*ND_, D_, pW1 + (size_t)l*D_*HID_, HID_,
                  0.f, pz1 + (size_t)l*NH1_, HID_, pb1 + l*HID_, 0, pgl + (size_t)l*NH1_, 1);
            // hout = hmid + gl@W2 + b2 ; abuf = LN_next(hout)  (split 16 -> reduce_ln)
            gemmx(0,0, NT_, D_, HID_, 16, 1.f, pgl + (size_t)l*NH1_, HID_, pW2 + (size_t)l*HID_*D_, D_, 0.f, 0, 0, 0);
            reduce_ln<<<NT_, 256>>>(h_work, 16, pb2 + l*D_, hmid, hout, nls, nlb, pabuf);
        }
        // logits: batched over B via blockIdx.z
        {
            dim3 g(V_ / 64, 1, B_);
            gemm64<0,0><<<g,256>>>(128, V_, D_, 1.f, pabuf, D_, Whead, V_,
                                   0.f, out + (size_t)off * V_, V_, bhead, h_work,
                                   1, (size_t)S_*D_, (size_t)(NCH_*S_)*V_, 0, 0, 0);
        }

        // ---------------- backward ----------------
        smax_dlog<<<NT_, 512>>>(out, x, off, pdlog);
        gemmx(0,1, NT_, D_, V_, 20, 1.f, pdlog, V_, Whead, V_, 0.f, 0, 0, 0);
        ln_bwd_f<<<NT_, 256>>>(phfin, h_work, 20, lnfs, pdh, 0);

        for (int l = L_-1; l >= 0; l--) {
            // dtH = (dh@W2^T) * dgelu(z1)   (unsplit, grid 64, mode 2)
            gemmx(0,1, NT_, HID_, D_, 1, 1.f, pdh, D_, pW2 + (size_t)l*HID_*D_, D_,
                  0.f, pdtH, HID_, 0, pz1 + (size_t)l*NH1_, 0, 2);
            // W2 -= LR * gl^T @ dh   (unsplit, grid 128, fused SGD)
            gemmx(1,0, HID_, D_, NT_, 1, -LR_, pgl + (size_t)l*NH1_, HID_, pdh, D_,
                  1.f, pW2 + (size_t)l*HID_*D_, D_, 0);
            bias2_sgd<<<(D_+HID_)/256, 256>>>(pdh, pdtH, pb2 + l*D_, pb1 + l*HID_);
            // dtD(work) = dtH @ W1^T (pre-update W1), split 16 -> ln2 bwd accumulate
            gemmx(0,1, NT_, D_, HID_, 16, 1.f, pdtH, HID_, pW1 + (size_t)l*D_*HID_, HID_, 0.f, 0, 0, 0);
            ln_bwd_f<<<NT_, 256>>>(phmid + (size_t)l*ND_, h_work, 16, ln2s + l*D_, pdh, 1);
            // W1 -= LR * m^T @ dtH   (unsplit, grid 128, fused SGD; after dtD used old W1)
            gemmx(1,0, D_, HID_, NT_, 1, -LR_, pm + (size_t)l*ND_, D_, pdtH, HID_,
                  1.f, pW1 + (size_t)l*D_*HID_, HID_, 0);

            // dob(work) = dh @ Wo^T  (split 16; attn_bwd1 reduces inline)
            gemmx(0,1, NT_, D_, D_, 16, 1.f, pdh, D_, Wo + (size_t)l*D_*D_, D_, 0.f, 0, 0, 0);
            attn_bwd1<<<dim3(S_,NH_,B_), 256>>>(pqkv + (size_t)l*NQ_, patt + (size_t)l*NA_,
                                                h_work, 16, pdob, pds, pdqkv);
            attn_bwd2<<<dim3(S_,NH_,B_), 256>>>(pqkv + (size_t)l*NQ_, patt + (size_t)l*NA_,
                                                pdob, pds, pdqkv);
            // dtD(work) = dqkv @ Wqkv^T, split 8 -> ln1 bwd accumulate
            gemmx(0,1, NT_, D_, 3*D_, 8, 1.f, pdqkv, 3*D_, Wqkv + (size_t)l*D_*3*D_, 3*D_, 0.f, 0, 0, 0);
            ln_bwd_f<<<NT_, 256>>>(ph + (size_t)l*ND_, h_work, 8, ln1s + l*D_, pdh, 1);
        }
    }
    (void)in_sizes; (void)n_in; (void)out_size;
}

// round 13
// speedup vs baseline: 1.1489x; 1.1489x over previous
#include <cuda_runtime.h>
#include <math.h>
#include <stdint.h>

#define D_    512
#define HID_  2048
#define L_    4
#define V_    32000
#define B_    2
#define T_    1025
#define S_    128
#define NH_   8
#define DH_   64
#define NT_   256
#define NCH_  8
#define LR_   0.0003f
#define ASC_  0.125f

#define ND_  (NT_*D_)
#define NH1_ (NT_*HID_)
#define NQ_  (NT_*3*D_)
#define NA_  (B_*NH_*S_*S_)
#define MND_ 131072           // 256*512

// ---------------- device scratch ----------------
__device__ float g_W1[L_*D_*HID_];
__device__ float g_W2[L_*HID_*D_];
__device__ float g_b1[L_*HID_];
__device__ float g_b2[L_*D_];
__device__ float g_h[L_*ND_];
__device__ float g_hmid[L_*ND_];
__device__ float g_hfin[ND_];
__device__ float g_m[L_*ND_];
__device__ float g_qkv[L_*NQ_];
__device__ float g_att[L_*NA_];
__device__ float g_z1[L_*NH1_];
__device__ float g_gl[L_*NH1_];
__device__ float g_abuf[ND_];
__device__ float g_obuf[ND_];
__device__ float g_dh[ND_];
__device__ float g_dtH[NH1_];
__device__ float g_dob[ND_];
__device__ float g_dqkv[NQ_];
__device__ float g_ds[NA_];
__device__ float g_dlog[NT_*V_];
__device__ float g_work[8*1024*1024];     // split-K partials (32 MB)

// ---------------- fast-math helpers ----------------
__device__ __forceinline__ float ftanh_(float u) {
    u = fminf(fmaxf(u, -15.f), 15.f);
    float e = __expf(2.f * u);
    return __fdividef(e - 1.f, e + 1.f);
}
__device__ __forceinline__ float gelu_f(float x) {
    float u = 0.7978845608028654f * (x + 0.044715f * x * x * x);
    return 0.5f * x * (1.f + ftanh_(u));
}
__device__ __forceinline__ float dgelu_f(float x) {
    float x2 = x * x;
    float u = 0.7978845608028654f * (x + 0.044715f * x * x2);
    float t = ftanh_(u);
    return 0.5f * (1.f + t)
         + 0.5f * x * (1.f - t * t) * 0.7978845608028654f * (1.f + 3.f * 0.044715f * x2);
}
__device__ __forceinline__ float f2tf_f(float f) {
    uint32_t u;
    asm("cvt.rna.tf32.f32 %0, %1;" : "=r"(u) : "f"(f));
    return __uint_as_float(u);
}

// ---------------- two-level block reductions (2 syncs each) ----------------
template<int NW>
__device__ __forceinline__ float bsum(float v, volatile float* sh) {
    #pragma unroll
    for (int o = 16; o; o >>= 1) v += __shfl_down_sync(0xffffffffu, v, o);
    if ((threadIdx.x & 31) == 0) sh[threadIdx.x >> 5] = v;
    __syncthreads();
    float r = sh[0];
    #pragma unroll
    for (int k = 1; k < NW; k++) r += sh[k];
    __syncthreads();
    return r;
}
template<int NW>
__device__ __forceinline__ float bmax(float v, volatile float* sh) {
    #pragma unroll
    for (int o = 16; o; o >>= 1) v = fmaxf(v, __shfl_down_sync(0xffffffffu, v, o));
    if ((threadIdx.x & 31) == 0) sh[threadIdx.x >> 5] = v;
    __syncthreads();
    float r = sh[0];
    #pragma unroll
    for (int k = 1; k < NW; k++) r = fmaxf(r, sh[k]);
    __syncthreads();
    return r;
}

// ---------------- 128x64x16 tf32 tensor-core GEMM (2 CTAs/SM) ----------------
// batched==0: gridDim.z = split-K count (nz>1 -> raw partials to work)
// batched==1: gridDim.z = batch index; full K; A/C offset by z strides
// nz==1: C = alpha*acc + bias? + beta*C
#define ASTR 136
#define BSTR 72
template<int TA, int TB>
__global__ void __launch_bounds__(256) gemm64(
    int M, int N, int K, float alpha,
    const float* __restrict__ A, int lda,
    const float* __restrict__ B, int ldb,
    float beta, float* __restrict__ C, int ldc,
    const float* __restrict__ bias, float* __restrict__ work,
    int batched, size_t sAz, size_t sCz)
{
    __shared__ __align__(16) float As[2][16*ASTR];
    __shared__ __align__(16) float Bs[2][16*BSTR];
    const int tid = threadIdx.x;
    const int m0 = blockIdx.y * 128, n0 = blockIdx.x * 64;
    const int z = blockIdx.z;
    const int nz = batched ? 1 : gridDim.z;
    const int kslice = batched ? K : (K / gridDim.z);
    const int kbeg = batched ? 0 : z * kslice;
    if (batched) { A += (size_t)z * sAz; C += (size_t)z * sCz; }

    const int a_r = TA ? (tid >> 4) : (tid >> 1);
    const int a_c = TA ? ((tid & 15) * 8) : ((tid & 1) * 8);
    const int b_r = TB ? (tid >> 2) : (tid >> 4);
    const int b_c = TB ? ((tid & 3) * 4) : ((tid & 15) * 4);

    float4 pa0, pa1, pb0;

    auto ldg = [&](int kk) {
        const float* pa = TA ? (A + (size_t)(kk + a_r) * lda + m0 + a_c)
                             : (A + (size_t)(m0 + a_r) * lda + kk + a_c);
        pa0 = *(const float4*)pa; pa1 = *(const float4*)(pa + 4);
        const float* pb = TB ? (B + (size_t)(n0 + b_r) * ldb + kk + b_c)
                             : (B + (size_t)(kk + b_r) * ldb + n0 + b_c);
        pb0 = *(const float4*)pb;
    };
    auto sts = [&](int buf) {
        float va[8] = {pa0.x,pa0.y,pa0.z,pa0.w,pa1.x,pa1.y,pa1.z,pa1.w};
        float vb[4] = {pb0.x,pb0.y,pb0.z,pb0.w};
        #pragma unroll
        for (int i = 0; i < 8; i++) va[i] = f2tf_f(va[i]);
        #pragma unroll
        for (int i = 0; i < 4; i++) vb[i] = f2tf_f(vb[i]);
        if (!TA) {
            #pragma unroll
            for (int i = 0; i < 8; i++) As[buf][(a_c + i) * ASTR + a_r] = va[i];
        } else {
            float4 w0 = {va[0],va[1],va[2],va[3]}, w1 = {va[4],va[5],va[6],va[7]};
            *(float4*)&As[buf][a_r * ASTR + a_c]     = w0;
            *(float4*)&As[buf][a_r * ASTR + a_c + 4] = w1;
        }
        if (!TB) {
            float4 w0 = {vb[0],vb[1],vb[2],vb[3]};
            *(float4*)&Bs[buf][b_r * BSTR + b_c] = w0;
        } else {
            #pragma unroll
            for (int i = 0; i < 4; i++) Bs[buf][(b_c + i) * BSTR + b_r] = vb[i];
        }
    };

    const int warp = tid >> 5, lane = tid & 31;
    const int mb = (warp >> 1) * 32;
    const int nb = (warp & 1) * 32;
    const int fr = lane >> 2, fq = lane & 3;

    float acc[2][4][4];
    #pragma unroll
    for (int i = 0; i < 2; i++)
        #pragma unroll
        for (int j = 0; j < 4; j++)
            #pragma unroll
            for (int e = 0; e < 4; e++) acc[i][j][e] = 0.f;

    ldg(kbeg); sts(0); __syncthreads();
    const int KT = kslice >> 4;
    for (int kt = 0; kt < KT; kt++) {
        int buf = kt & 1;
        if (kt + 1 < KT) ldg(kbeg + (kt + 1) * 16);
        #pragma unroll
        for (int ks = 0; ks < 16; ks += 8) {
            uint32_t af[2][4], bf[4][2];
            #pragma unroll
            for (int i = 0; i < 2; i++) {
                const float* ap = &As[buf][(ks + fq) * ASTR + mb + 16*i + fr];
                af[i][0] = __float_as_uint(ap[0]);
                af[i][1] = __float_as_uint(ap[8]);
                af[i][2] = __float_as_uint(ap[4*ASTR]);
                af[i][3] = __float_as_uint(ap[4*ASTR + 8]);
            }
            #pragma unroll
            for (int j = 0; j < 4; j++) {
                const float* bp = &Bs[buf][(ks + fq) * BSTR + nb + 8*j + fr];
                bf[j][0] = __float_as_uint(bp[0]);
                bf[j][1] = __float_as_uint(bp[4*BSTR]);
            }
            #pragma unroll
            for (int i = 0; i < 2; i++)
                #pragma unroll
                for (int j = 0; j < 4; j++)
                    asm volatile(
                        "mma.sync.aligned.m16n8k8.row.col.f32.tf32.tf32.f32 "
                        "{%0,%1,%2,%3}, {%4,%5,%6,%7}, {%8,%9}, {%0,%1,%2,%3};"
                        : "+f"(acc[i][j][0]), "+f"(acc[i][j][1]),
                          "+f"(acc[i][j][2]), "+f"(acc[i][j][3])
                        : "r"(af[i][0]), "r"(af[i][1]), "r"(af[i][2]), "r"(af[i][3]),
                          "r"(bf[j][0]), "r"(bf[j][1]));
        }
        if (kt + 1 < KT) sts(buf ^ 1);
        __syncthreads();
    }

    if (nz > 1) {
        float* W = work + (size_t)z * M * N;
        #pragma unroll
        for (int i = 0; i < 2; i++) {
            int row = m0 + mb + 16*i + fr;
            #pragma unroll
            for (int j = 0; j < 4; j++) {
                int col = n0 + nb + 8*j + 2*fq;
                float2 v0 = {acc[i][j][0], acc[i][j][1]};
                float2 v1 = {acc[i][j][2], acc[i][j][3]};
                *(float2*)&W[(size_t)row * N + col]       = v0;
                *(float2*)&W[(size_t)(row + 8) * N + col] = v1;
            }
        }
    } else {
        #pragma unroll
        for (int i = 0; i < 2; i++) {
            int row = m0 + mb + 16*i + fr;
            #pragma unroll
            for (int j = 0; j < 4; j++) {
                int col = n0 + nb + 8*j + 2*fq;
                float v[4];
                #pragma unroll
                for (int e = 0; e < 4; e++) v[e] = alpha * acc[i][j][e];
                if (bias) {
                    float b0 = bias[col], b1 = bias[col + 1];
                    v[0] += b0; v[1] += b1; v[2] += b0; v[3] += b1;
                }
                float* c0 = C + (size_t)row * ldc + col;
                float* c1 = C + (size_t)(row + 8) * ldc + col;
                if (beta != 0.f) {
                    v[0] += beta * c0[0]; v[1] += beta * c0[1];
                    v[2] += beta * c1[0]; v[3] += beta * c1[1];
                }
                float2 v0 = {v[0], v[1]}, v1 = {v[2], v[3]};
                *(float2*)c0 = v0; *(float2*)c1 = v1;
            }
        }
    }
}

// ---------------- split-K reduce (float4-vectorized, fused epilogues) ----------------
__global__ void __launch_bounds__(256) reduce_k(
    const float* __restrict__ work, int nz, int MN, int N,
    float alpha, float beta, float* __restrict__ C,
    const float* __restrict__ bias,
    const float* __restrict__ zbuf, float* __restrict__ gl, int mode)
{
    int i4 = blockIdx.x * 256 + threadIdx.x;
    int MN4 = MN >> 2;
    const float4* w4 = (const float4*)work;
    float4 s = {0.f, 0.f, 0.f, 0.f};
    for (int zz = 0; zz < nz; zz++) {
        float4 p = w4[(size_t)zz * MN4 + i4];
        s.x += p.x; s.y += p.y; s.z += p.z; s.w += p.w;
    }
    s.x *= alpha; s.y *= alpha; s.z *= alpha; s.w *= alpha;
    int i = i4 << 2;
    int col = i % N;
    if (mode == 1) {
        float4 b4 = *(const float4*)&bias[col];
        s.x += b4.x; s.y += b4.y; s.z += b4.z; s.w += b4.w;
        *(float4*)&C[i] = s;
        float4 g = {gelu_f(s.x), gelu_f(s.y), gelu_f(s.z), gelu_f(s.w)};
        *(float4*)&gl[i] = g;
    } else if (mode == 2) {
        float4 z4 = *(const float4*)&zbuf[i];
        s.x *= dgelu_f(z4.x); s.y *= dgelu_f(z4.y);
        s.z *= dgelu_f(z4.z); s.w *= dgelu_f(z4.w);
        *(float4*)&C[i] = s;
    } else {
        if (bias) {
            float4 b4 = *(const float4*)&bias[col];
            s.x += b4.x; s.y += b4.y; s.z += b4.z; s.w += b4.w;
        }
        if (beta != 0.f) {
            float4 c4 = *(const float4*)&C[i];
            s.x += beta * c4.x; s.y += beta * c4.y;
            s.z += beta * c4.z; s.w += beta * c4.w;
        }
        *(float4*)&C[i] = s;
    }
}

// ---------------- reduce partials + residual + bias, then LayerNorm ----------------
__global__ void __launch_bounds__(256) reduce_ln(
    const float* __restrict__ work, int nz,
    const float* __restrict__ bias, const float* __restrict__ res,
    float* __restrict__ hout,
    const float* __restrict__ ls, const float* __restrict__ lb,
    float* __restrict__ y)
{
    __shared__ float sh[8];
    int row = blockIdx.x, tid = threadIdx.x;
    size_t base = (size_t)row * D_;
    int c = tid * 2;
    float2 v = {0.f, 0.f};
    for (int z = 0; z < nz; z++) {
        float2 p = *(const float2*)&work[(size_t)z * MND_ + base + c];
        v.x += p.x; v.y += p.y;
    }
    float2 b2 = *(const float2*)&bias[c];
    float2 r2 = *(const float2*)&res[base + c];
    v.x += b2.x + r2.x; v.y += b2.y + r2.y;
    *(float2*)&hout[base + c] = v;

    float mean = bsum<8>(v.x + v.y, sh) * (1.f / D_);
    float d0 = v.x - mean, d1 = v.y - mean;
    float var = bsum<8>(d0 * d0 + d1 * d1, sh) * (1.f / D_);
    float rstd = rsqrtf(var + 1e-5f);
    float2 s2 = *(const float2*)&ls[c];
    float2 o2 = *(const float2*)&lb[c];
    float2 out = {d0 * rstd * s2.x + o2.x, d1 * rstd * s2.y + o2.y};
    *(float2*)&y[base + c] = out;
}

// ---------------- fused embed + LN1(layer0) ----------------
__global__ void __launch_bounds__(256) embed_ln(const int* __restrict__ x,
    const float* __restrict__ emb, const float* __restrict__ pos, int off,
    float* __restrict__ h, const float* __restrict__ ls, const float* __restrict__ lb,
    float* __restrict__ y)
{
    __shared__ float sh[8];
    int row = blockIdx.x, tid = threadIdx.x;
    int b = row >> 7, s = row & 127;
    int tok = x[b * T_ + off + s];
    size_t base = (size_t)row * D_;
    int c = tid * 2;
    float2 e2 = *(const float2*)&emb[(size_t)tok * D_ + c];
    float2 p2 = *(const float2*)&pos[s * D_ + c];
    float2 v = {e2.x + p2.x, e2.y + p2.y};
    *(float2*)&h[base + c] = v;

    float mean = bsum<8>(v.x + v.y, sh) * (1.f / D_);
    float d0 = v.x - mean, d1 = v.y - mean;
    float var = bsum<8>(d0 * d0 + d1 * d1, sh) * (1.f / D_);
    float rstd = rsqrtf(var + 1e-5f);
    float2 s2 = *(const float2*)&ls[c];
    float2 o2 = *(const float2*)&lb[c];
    float2 out = {d0 * rstd * s2.x + o2.x, d1 * rstd * s2.y + o2.y};
    *(float2*)&y[base + c] = out;
}

// ---------------- LN backward with fused split-K partial sum ----------------
__global__ void __launch_bounds__(256) ln_bwd_f(const float* __restrict__ x,
    const float* __restrict__ work, int nz, const float* __restrict__ s,
    float* __restrict__ dacc, int accum)
{
    __shared__ float sh[8];
    int row = blockIdx.x, tid = threadIdx.x;
    size_t base = (size_t)row * D_;
    int c = tid * 2;
    float2 dy = {0.f, 0.f};
    for (int z = 0; z < nz; z++) {
        float2 p = *(const float2*)&work[(size_t)z * MND_ + base + c];
        dy.x += p.x; dy.y += p.y;
    }
    float2 xv = *(const float2*)&x[base + c];
    float mean = bsum<8>(xv.x + xv.y, sh) * (1.f / D_);
    float d0 = xv.x - mean, d1 = xv.y - mean;
    float var = bsum<8>(d0 * d0 + d1 * d1, sh) * (1.f / D_);
    float rstd = rsqrtf(var + 1e-5f);
    float xh0 = d0 * rstd, xh1 = d1 * rstd;
    float2 s2 = *(const float2*)&s[c];
    float g0 = s2.x * dy.x, g1 = s2.y * dy.y;
    float t1 = bsum<8>(g0 + g1, sh) * (1.f / D_);
    float t2 = bsum<8>(g0 * xh0 + g1 * xh1, sh) * (1.f / D_);
    float dx0 = rstd * (g0 - t1 - xh0 * t2);
    float dx1 = rstd * (g1 - t1 - xh1 * t2);
    float2* ar = (float2*)&dacc[base + c];
    if (accum) { float2 old = *ar; ar->x = old.x + dx0; ar->y = old.y + dx1; }
    else       { float2 nv = {dx0, dx1}; *ar = nv; }
}

// ---------------- attention forward (256 thr, 4-way parallel AV loop) ----------------
__global__ void __launch_bounds__(256) attn_fwd(const float* __restrict__ qkv,
    float* __restrict__ att, float* __restrict__ obuf)
{
    __shared__ float qs[DH_]; __shared__ float sc[S_]; __shared__ float sh[8];
    __shared__ float part[4][DH_ + 1];
    int qi = blockIdx.x, h = blockIdx.y, b = blockIdx.z, tid = threadIdx.x;
    int row = b * S_ + qi;
    if (tid < DH_) qs[tid] = qkv[(size_t)row * (3*D_) + h * DH_ + tid];
    __syncthreads();
    float sj = -1e30f;
    if (tid <= qi) {
        const float* kp = qkv + (size_t)(b * S_ + tid) * (3*D_) + D_ + h * DH_;
        float a = 0.f;
        #pragma unroll
        for (int d = 0; d < DH_; d++) a += qs[d] * kp[d];
        sj = a * ASC_;
    }
    float mx = bmax<8>(sj, sh);
    float e = (tid <= qi) ? __expf(sj - mx) : 0.f;
    float tot = bsum<8>(e, sh);
    float a = e / tot;
    size_t arow = ((size_t)(b * NH_ + h) * S_ + qi) * S_;
    if (tid < S_) { att[arow + tid] = a; sc[tid] = a; }
    __syncthreads();
    int d = tid & (DH_ - 1), p = tid >> 6;
    float acc = 0.f;
    for (int j = p; j <= qi; j += 4)
        acc += sc[j] * qkv[(size_t)(b * S_ + j) * (3*D_) + 2*D_ + h * DH_ + d];
    part[p][d] = acc;
    __syncthreads();
    if (tid < DH_)
        obuf[(size_t)row * D_ + h * DH_ + tid] =
            (part[0][tid] + part[1][tid]) + (part[2][tid] + part[3][tid]);
}

// ---------------- attention backward 1 (256 thr, fused dob partial-sum) ----------------
__global__ void __launch_bounds__(256) attn_bwd1(const float* __restrict__ qkv,
    const float* __restrict__ att, const float* __restrict__ work, int nz,
    float* __restrict__ dob, float* __restrict__ dsbuf, float* __restrict__ dqkv)
{
    __shared__ float dov[DH_]; __shared__ float sc[S_]; __shared__ float sh[8];
    __shared__ float part[4][DH_ + 1];
    int qi = blockIdx.x, h = blockIdx.y, b = blockIdx.z, tid = threadIdx.x;
    int row = b * S_ + qi;
    if (tid < DH_) {
        size_t wi = (size_t)row * D_ + h * DH_ + tid;
        float s = 0.f;
        for (int z = 0; z < nz; z++) s += work[(size_t)z * MND_ + wi];
        dov[tid] = s;
        dob[wi] = s;
    }
    __syncthreads();
    size_t arow = ((size_t)(b * NH_ + h) * S_ + qi) * S_;
    float a = (tid < S_) ? att[arow + tid] : 0.f;
    float datt = 0.f;
    if (tid <= qi) {
        const float* vp = qkv + (size_t)(b * S_ + tid) * (3*D_) + 2*D_ + h * DH_;
        #pragma unroll
        for (int d = 0; d < DH_; d++) datt += dov[d] * vp[d];
    }
    float tot = bsum<8>(a * datt, sh);
    float ds = a * (datt - tot);
    if (tid < S_) { dsbuf[arow + tid] = ds; sc[tid] = ds; }
    __syncthreads();
    int d = tid & (DH_ - 1), p = tid >> 6;
    float acc = 0.f;
    for (int j = p; j <= qi; j += 4)
        acc += sc[j] * qkv[(size_t)(b * S_ + j) * (3*D_) + D_ + h * DH_ + d];
    part[p][d] = acc;
    __syncthreads();
    if (tid < DH_)
        dqkv[(size_t)row * (3*D_) + h * DH_ + tid] =
            ((part[0][tid] + part[1][tid]) + (part[2][tid] + part[3][tid])) * ASC_;
}

// ---------------- attention backward 2 (256 thr, 4-way parallel q loop) ----------------
__global__ void __launch_bounds__(256) attn_bwd2(const float* __restrict__ qkv,
    const float* __restrict__ att, const float* __restrict__ dob,
    const float* __restrict__ dsbuf, float* __restrict__ dqkv)
{
    __shared__ float pk[4][DH_ + 1], pv[4][DH_ + 1];
    int j = blockIdx.x, h = blockIdx.y, b = blockIdx.z, tid = threadIdx.x;
    int d = tid & (DH_ - 1), p = tid >> 6;
    size_t bh = (size_t)(b * NH_ + h) * S_;
    float dk = 0.f, dv = 0.f;
    for (int q = j + p; q < S_; q += 4) {
        float ds = dsbuf[(bh + q) * S_ + j];
        float a  = att[(bh + q) * S_ + j];
        dk += ds * qkv[(size_t)(b * S_ + q) * (3*D_) + h * DH_ + d];
        dv += a  * dob[(size_t)(b * S_ + q) * D_ + h * DH_ + d];
    }
    pk[p][d] = dk; pv[p][d] = dv;
    __syncthreads();
    if (tid < DH_) {
        float dks = (pk[0][tid] + pk[1][tid]) + (pk[2][tid] + pk[3][tid]);
        float dvs = (pv[0][tid] + pv[1][tid]) + (pv[2][tid] + pv[3][tid]);
        dqkv[(size_t)(b * S_ + j) * (3*D_) + D_   + h * DH_ + tid] = dks * ASC_;
        dqkv[(size_t)(b * S_ + j) * (3*D_) + 2*D_ + h * DH_ + tid] = dvs;
    }
}

// ---------------- both bias SGD updates in one launch ----------------
__global__ void __launch_bounds__(256) bias2_sgd(const float* __restrict__ dh,
    const float* __restrict__ dtH, float* __restrict__ b2, float* __restrict__ b1)
{
    int c = blockIdx.x * 256 + threadIdx.x;
    if (c < D_) {
        float s = 0.f;
        for (int i = 0; i < NT_; i++) s += dh[(size_t)i * D_ + c];
        b2[c] -= LR_ * s;
    } else {
        int c1 = c - D_;
        float s = 0.f;
        for (int i = 0; i < NT_; i++) s += dtH[(size_t)i * HID_ + c1];
        b1[c1] -= LR_ * s;
    }
}

// ---------------- fused online softmax stats + dlogits (512 thr, float4) ----------------
__global__ void __launch_bounds__(512) smax_dlog(const float* __restrict__ out,
    const int* __restrict__ x, int off, float* __restrict__ dl)
{
    __shared__ float rm[512], rs[512];
    int i = blockIdx.x, tid = threadIdx.x;
    int b = i >> 7, s = i & 127;
    const float* lp = out + ((size_t)(b * (NCH_*S_) + off + s)) * V_;
    const float4* lp4 = (const float4*)lp;

    float m = -1e30f, sum = 0.f;
    for (int v4 = tid; v4 < V_/4; v4 += 512) {
        float4 q = lp4[v4];
        float vals[4] = {q.x, q.y, q.z, q.w};
        #pragma unroll
        for (int e = 0; e < 4; e++) {
            float v = vals[e];
            if (v > m) { sum *= __expf(m - v); m = v; }
            sum += __expf(v - m);
        }
    }
    rm[tid] = m; rs[tid] = sum; __syncthreads();
    for (int w = 256; w > 0; w >>= 1) {
        if (tid < w) {
            float m1 = rm[tid], m2 = rm[tid + w];
            float M = fmaxf(m1, m2);
            rs[tid] = rs[tid] * __expf(m1 - M) + rs[tid + w] * __expf(m2 - M);
            rm[tid] = M;
        }
        __syncthreads();
    }
    m = rm[0];
    float rinv = __fdividef(1.f, rs[0]);
    const float invNT = 1.f / NT_;
    int tgt = x[b * T_ + off + s + 1];

    float4* dl4 = (float4*)(dl + (size_t)i * V_);
    for (int v4 = tid; v4 < V_/4; v4 += 512) {
        float4 q = lp4[v4];
        int vb = v4 * 4;
        float4 p;
        p.x = (__expf(q.x - m) * rinv - (vb + 0 == tgt ? 1.f : 0.f)) * invNT;
        p.y = (__expf(q.y - m) * rinv - (vb + 1 == tgt ? 1.f : 0.f)) * invNT;
        p.z = (__expf(q.z - m) * rinv - (vb + 2 == tgt ? 1.f : 0.f)) * invNT;
        p.w = (__expf(q.w - m) * rinv - (vb + 3 == tgt ? 1.f : 0.f)) * invNT;
        dl4[v4] = p;
    }
}

// ---------------- segmented param copy (one launch) ----------------
#define NW1_ (L_*D_*HID_)
#define NW2_ (L_*HID_*D_)
#define NB1_ (L_*HID_)
#define NB2_ (L_*D_)
__global__ void __launch_bounds__(256) copy_params(
    const float* __restrict__ w1, const float* __restrict__ w2,
    const float* __restrict__ b1, const float* __restrict__ b2,
    float* __restrict__ pw1, float* __restrict__ pw2,
    float* __restrict__ pb1, float* __restrict__ pb2)
{
    int i = blockIdx.x * 256 + threadIdx.x;
    if (i < NW1_) { pw1[i] = w1[i]; }
    int j = i - NW1_;
    if (j >= 0 && j < NW2_) { pw2[j] = w2[j]; }
    int k = i - NW1_ - NW2_;
    if (k >= 0 && k < NB1_) { pb1[k] = b1[k]; }
    int l = i - NW1_ - NW2_ - NB1_;
    if (l >= 0 && l < NB2_) { pb2[l] = b2[l]; }
}

// ---------------- host ----------------
static float* P(const void* sym) { void* p = 0; cudaGetSymbolAddress(&p, sym); return (float*)p; }

static float* h_work;

static void gemmx(int TA, int TB, int M, int N, int K, int nz, float alpha,
                  const float* A, int lda, const float* B, int ldb,
                  float beta, float* C, int ldc, const float* bias)
{
    dim3 g(N / 64, M / 128, nz);
    if (!TA && !TB)      gemm64<0,0><<<g,256>>>(M,N,K,alpha,A,lda,B,ldb,beta,C,ldc,bias,h_work,0,0,0);
    else if (!TA && TB)  gemm64<0,1><<<g,256>>>(M,N,K,alpha,A,lda,B,ldb,beta,C,ldc,bias,h_work,0,0,0);
    else if (TA && !TB)  gemm64<1,0><<<g,256>>>(M,N,K,alpha,A,lda,B,ldb,beta,C,ldc,bias,h_work,0,0,0);
    else                 gemm64<1,1><<<g,256>>>(M,N,K,alpha,A,lda,B,ldb,beta,C,ldc,bias,h_work,0,0,0);
}

extern "C" void kernel_launch(void* const* d_in, const int* in_sizes, int n_in,
                              void* d_out, int out_size)
{
    const int*   x     = (const int*)  d_in[0];
    const float* emb   = (const float*)d_in[1];
    const float* pos   = (const float*)d_in[2];
    const float* ln1s  = (const float*)d_in[3];
    const float* ln1b  = (const float*)d_in[4];
    const float* Wqkv  = (const float*)d_in[5];
    const float* bqkv  = (const float*)d_in[6];
    const float* Wo    = (const float*)d_in[7];
    const float* bo    = (const float*)d_in[8];
    const float* ln2s  = (const float*)d_in[9];
    const float* ln2b  = (const float*)d_in[10];
    const float* W1i   = (const float*)d_in[11];
    const float* b1i   = (const float*)d_in[12];
    const float* W2i   = (const float*)d_in[13];
    const float* b2i   = (const float*)d_in[14];
    const float* lnfs  = (const float*)d_in[15];
    const float* lnfb  = (const float*)d_in[16];
    const float* Whead = (const float*)d_in[17];
    const float* bhead = (const float*)d_in[18];
    float* out = (float*)d_out;

    float *pW1 = P(g_W1), *pW2 = P(g_W2), *pb1 = P(g_b1), *pb2 = P(g_b2);
    float *ph = P(g_h), *phmid = P(g_hmid), *phfin = P(g_hfin), *pm = P(g_m);
    float *pqkv = P(g_qkv), *patt = P(g_att), *pz1 = P(g_z1), *pgl = P(g_gl);
    float *pabuf = P(g_abuf), *pobuf = P(g_obuf), *pdh = P(g_dh);
    float *pdtH = P(g_dtH), *pdob = P(g_dob);
    float *pdqkv = P(g_dqkv), *pds = P(g_ds), *pdlog = P(g_dlog);
    h_work = P(g_work);

    const int copyN = NW1_ + NW2_ + NB1_ + NB2_;
    copy_params<<<(copyN + 255)/256, 256>>>(W1i, W2i, b1i, b2i, pW1, pW2, pb1, pb2);

    for (int c = 0; c < NCH_; c++) {
        const int off = c * S_;

        // ---------------- forward ----------------
        embed_ln<<<NT_, 256>>>(x, emb, pos, off, ph, ln1s, ln1b, pabuf);
        for (int l = 0; l < L_; l++) {
            float* hin = ph + (size_t)l * ND_;
            float* hmid = phmid + (size_t)l * ND_;
            float* hout = (l < L_-1) ? ph + (size_t)(l+1)*ND_ : phfin;
            const float* nls = (l < L_-1) ? ln1s + (l+1)*D_ : lnfs;
            const float* nlb = (l < L_-1) ? ln1b + (l+1)*D_ : lnfb;

            gemmx(0,0, NT_, 3*D_, D_, 8, 1.f, pabuf, D_, Wqkv + (size_t)l*D_*3*D_, 3*D_, 0.f, 0, 0, 0);
            reduce_k<<<NQ_/1024, 256>>>(h_work, 8, NQ_, 3*D_, 1.f, 0.f,
                                        pqkv + (size_t)l*NQ_, bqkv + l*3*D_, 0, 0, 0);
            attn_fwd<<<dim3(S_,NH_,B_), 256>>>(pqkv + (size_t)l*NQ_, patt + (size_t)l*NA_, pobuf);
            gemmx(0,0, NT_, D_, D_, 16, 1.f, pobuf, D_, Wo + (size_t)l*D_*D_, D_, 0.f, 0, 0, 0);
            reduce_ln<<<NT_, 256>>>(h_work, 16, bo + l*D_, hin, hmid,
                                    ln2s + l*D_, ln2b + l*D_, pm + (size_t)l*ND_);
            gemmx(0,0, NT_, HID_, D_, 4, 1.f, pm + (size_t)l*ND_, D_, pW1 + (size_t)l*D_*HID_, HID_, 0.f, 0, 0, 0);
            reduce_k<<<NH1_/1024, 256>>>(h_work, 4, NH1_, HID_, 1.f, 0.f,
                                         pz1 + (size_t)l*NH1_, pb1 + l*HID_,
                                         0, pgl + (size_t)l*NH1_, 1);
            gemmx(0,0, NT_, D_, HID_, 16, 1.f, pgl + (size_t)l*NH1_, HID_, pW2 + (size_t)l*HID_*D_, D_, 0.f, 0, 0, 0);
            reduce_ln<<<NT_, 256>>>(h_work, 16, pb2 + l*D_, hmid, hout, nls, nlb, pabuf);
        }
        // logits: batched over B via blockIdx.z
        {
            dim3 g(V_ / 64, 1, B_);
            gemm64<0,0><<<g,256>>>(128, V_, D_, 1.f, pabuf, D_, Whead, V_,
                                   0.f, out + (size_t)off * V_, V_, bhead, h_work,
                                   1, (size_t)S_*D_, (size_t)(NCH_*S_)*V_);
        }

        // ---------------- backward ----------------
        smax_dlog<<<NT_, 512>>>(out, x, off, pdlog);
        gemmx(0,1, NT_, D_, V_, 20, 1.f, pdlog, V_, Whead, V_, 0.f, 0, 0, 0);
        ln_bwd_f<<<NT_, 256>>>(phfin, h_work, 20, lnfs, pdh, 0);

        for (int l = L_-1; l >= 0; l--) {
            // dtH = (dh @ W2^T) * dgelu(z1)  (split 4 + reduce mode 2)
            gemmx(0,1, NT_, HID_, D_, 4, 1.f, pdh, D_, pW2 + (size_t)l*HID_*D_, D_, 0.f, 0, 0, 0);
            reduce_k<<<NH1_/1024, 256>>>(h_work, 4, NH1_, HID_, 1.f, 0.f, pdtH, 0,
                                         pz1 + (size_t)l*NH1_, 0, 2);
            // W2 -= LR * gl^T @ dh   (unsplit grid 128, fused SGD epilogue)
            gemmx(1,0, HID_, D_, NT_, 1, -LR_, pgl + (size_t)l*NH1_, HID_, pdh, D_,
                  1.f, pW2 + (size_t)l*HID_*D_, D_, 0);
            bias2_sgd<<<(D_+HID_)/256, 256>>>(pdh, pdtH, pb2 + l*D_, pb1 + l*HID_);
            // dtD(work) = dtH @ W1^T (pre-update W1), split 16 -> ln2 bwd accumulate
            gemmx(0,1, NT_, D_, HID_, 16, 1.f, pdtH, HID_, pW1 + (size_t)l*D_*HID_, HID_, 0.f, 0, 0, 0);
            ln_bwd_f<<<NT_, 256>>>(phmid + (size_t)l*ND_, h_work, 16, ln2s + l*D_, pdh, 1);
            // W1 -= LR * m^T @ dtH   (unsplit grid 128, fused SGD; after dtD used old W1)
            gemmx(1,0, D_, HID_, NT_, 1, -LR_, pm + (size_t)l*ND_, D_, pdtH, HID_,
                  1.f, pW1 + (size_t)l*D_*HID_, HID_, 0);

            // dob(work) = dh @ Wo^T  (split 16; attn_bwd1 reduces inline)
            gemmx(0,1, NT_, D_, D_, 16, 1.f, pdh, D_, Wo + (size_t)l*D_*D_, D_, 0.f, 0, 0, 0);
            attn_bwd1<<<dim3(S_,NH_,B_), 256>>>(pqkv + (size_t)l*NQ_, patt + (size_t)l*NA_,
                                                h_work, 16, pdob, pds, pdqkv);
            attn_bwd2<<<dim3(S_,NH_,B_), 256>>>(pqkv + (size_t)l*NQ_, patt + (size_t)l*NA_,
                                                pdob, pds, pdqkv);
            // dtD(work) = dqkv @ Wqkv^T, split 16 -> ln1 bwd accumulate
            gemmx(0,1, NT_, D_, 3*D_, 16, 1.f, pdqkv, 3*D_, Wqkv + (size_t)l*D_*3*D_, 3*D_, 0.f, 0, 0, 0);
            ln_bwd_f<<<NT_, 256>>>(ph + (size_t)l*ND_, h_work, 16, ln1s + l*D_, pdh, 1);
        }
    }
    (void)in_sizes; (void)n_in; (void)out_size;
}

// round 14
// speedup vs baseline: 1.1805x; 1.0275x over previous
#include <cuda_runtime.h>
#include <math.h>
#include <stdint.h>

#define D_    512
#define HID_  2048
#define L_    4
#define V_    32000
#define B_    2
#define T_    1025
#define S_    128
#define NH_   8
#define DH_   64
#define NT_   256
#define NCH_  8
#define LR_   0.0003f
#define ASC_  0.125f

#define ND_  (NT_*D_)
#define NH1_ (NT_*HID_)
#define NQ_  (NT_*3*D_)
#define NA_  (B_*NH_*S_*S_)
#define MND_ 131072           // 256*512

// ---------------- device scratch ----------------
__device__ float g_W1[L_*D_*HID_];
__device__ float g_W2[L_*HID_*D_];
__device__ float g_b1[L_*HID_];
__device__ float g_b2[L_*D_];
__device__ float g_h[L_*ND_];
__device__ float g_hmid[L_*ND_];
__device__ float g_hfin[ND_];
__device__ float g_m[L_*ND_];
__device__ float g_qkv[L_*NQ_];
__device__ float g_att[L_*NA_];
__device__ float g_z1[L_*NH1_];
__device__ float g_gl[L_*NH1_];
__device__ float g_abuf[ND_];
__device__ float g_obuf[ND_];
__device__ float g_dh[ND_];
__device__ float g_dtH[NH1_];
__device__ float g_dob[ND_];
__device__ float g_dqkv[NQ_];
__device__ float g_ds[NA_];
__device__ float g_dlog[NT_*V_];
__device__ float g_work[8*1024*1024];     // split-K partials (32 MB)

// ---------------- fast-math helpers ----------------
__device__ __forceinline__ float ftanh_(float u) {
    u = fminf(fmaxf(u, -15.f), 15.f);
    float e = __expf(2.f * u);
    return __fdividef(e - 1.f, e + 1.f);
}
__device__ __forceinline__ float gelu_f(float x) {
    float u = 0.7978845608028654f * (x + 0.044715f * x * x * x);
    return 0.5f * x * (1.f + ftanh_(u));
}
__device__ __forceinline__ float dgelu_f(float x) {
    float x2 = x * x;
    float u = 0.7978845608028654f * (x + 0.044715f * x * x2);
    float t = ftanh_(u);
    return 0.5f * (1.f + t)
         + 0.5f * x * (1.f - t * t) * 0.7978845608028654f * (1.f + 3.f * 0.044715f * x2);
}
__device__ __forceinline__ float f2tf_f(float f) {
    uint32_t u;
    asm("cvt.rna.tf32.f32 %0, %1;" : "=r"(u) : "f"(f));
    return __uint_as_float(u);
}

// ---------------- two-level block reductions (2 syncs each) ----------------
template<int NW>
__device__ __forceinline__ float bsum(float v, volatile float* sh) {
    #pragma unroll
    for (int o = 16; o; o >>= 1) v += __shfl_down_sync(0xffffffffu, v, o);
    if ((threadIdx.x & 31) == 0) sh[threadIdx.x >> 5] = v;
    __syncthreads();
    float r = sh[0];
    #pragma unroll
    for (int k = 1; k < NW; k++) r += sh[k];
    __syncthreads();
    return r;
}
template<int NW>
__device__ __forceinline__ float bmax(float v, volatile float* sh) {
    #pragma unroll
    for (int o = 16; o; o >>= 1) v = fmaxf(v, __shfl_down_sync(0xffffffffu, v, o));
    if ((threadIdx.x & 31) == 0) sh[threadIdx.x >> 5] = v;
    __syncthreads();
    float r = sh[0];
    #pragma unroll
    for (int k = 1; k < NW; k++) r = fmaxf(r, sh[k]);
    __syncthreads();
    return r;
}

// ---------------- 128x64x16 tf32 tensor-core GEMM (2 CTAs/SM) ----------------
// batched==0: gridDim.z = split-K count (nz>1 -> raw partials to work)
// batched==1: gridDim.z = batch index; full K; A/C offset by z strides
// nz==1: C = alpha*acc + bias? + beta*C
#define ASTR 136
#define BSTR 72
template<int TA, int TB>
__global__ void __launch_bounds__(256) gemm64(
    int M, int N, int K, float alpha,
    const float* __restrict__ A, int lda,
    const float* __restrict__ B, int ldb,
    float beta, float* __restrict__ C, int ldc,
    const float* __restrict__ bias, float* __restrict__ work,
    int batched, size_t sAz, size_t sCz)
{
    __shared__ __align__(16) float As[2][16*ASTR];
    __shared__ __align__(16) float Bs[2][16*BSTR];
    const int tid = threadIdx.x;
    const int m0 = blockIdx.y * 128, n0 = blockIdx.x * 64;
    const int z = blockIdx.z;
    const int nz = batched ? 1 : gridDim.z;
    const int kslice = batched ? K : (K / gridDim.z);
    const int kbeg = batched ? 0 : z * kslice;
    if (batched) { A += (size_t)z * sAz; C += (size_t)z * sCz; }

    const int a_r = TA ? (tid >> 4) : (tid >> 1);
    const int a_c = TA ? ((tid & 15) * 8) : ((tid & 1) * 8);
    const int b_r = TB ? (tid >> 2) : (tid >> 4);
    const int b_c = TB ? ((tid & 3) * 4) : ((tid & 15) * 4);

    float4 pa0, pa1, pb0;

    auto ldg = [&](int kk) {
        const float* pa = TA ? (A + (size_t)(kk + a_r) * lda + m0 + a_c)
                             : (A + (size_t)(m0 + a_r) * lda + kk + a_c);
        pa0 = *(const float4*)pa; pa1 = *(const float4*)(pa + 4);
        const float* pb = TB ? (B + (size_t)(n0 + b_r) * ldb + kk + b_c)
                             : (B + (size_t)(kk + b_r) * ldb + n0 + b_c);
        pb0 = *(const float4*)pb;
    };
    auto sts = [&](int buf) {
        float va[8] = {pa0.x,pa0.y,pa0.z,pa0.w,pa1.x,pa1.y,pa1.z,pa1.w};
        float vb[4] = {pb0.x,pb0.y,pb0.z,pb0.w};
        #pragma unroll
        for (int i = 0; i < 8; i++) va[i] = f2tf_f(va[i]);
        #pragma unroll
        for (int i = 0; i < 4; i++) vb[i] = f2tf_f(vb[i]);
        if (!TA) {
            #pragma unroll
            for (int i = 0; i < 8; i++) As[buf][(a_c + i) * ASTR + a_r] = va[i];
        } else {
            float4 w0 = {va[0],va[1],va[2],va[3]}, w1 = {va[4],va[5],va[6],va[7]};
            *(float4*)&As[buf][a_r * ASTR + a_c]     = w0;
            *(float4*)&As[buf][a_r * ASTR + a_c + 4] = w1;
        }
        if (!TB) {
            float4 w0 = {vb[0],vb[1],vb[2],vb[3]};
            *(float4*)&Bs[buf][b_r * BSTR + b_c] = w0;
        } else {
            #pragma unroll
            for (int i = 0; i < 4; i++) Bs[buf][(b_c + i) * BSTR + b_r] = vb[i];
        }
    };

    const int warp = tid >> 5, lane = tid & 31;
    const int mb = (warp >> 1) * 32;
    const int nb = (warp & 1) * 32;
    const int fr = lane >> 2, fq = lane & 3;

    float acc[2][4][4];
    #pragma unroll
    for (int i = 0; i < 2; i++)
        #pragma unroll
        for (int j = 0; j < 4; j++)
            #pragma unroll
            for (int e = 0; e < 4; e++) acc[i][j][e] = 0.f;

    ldg(kbeg); sts(0); __syncthreads();
    const int KT = kslice >> 4;
    for (int kt = 0; kt < KT; kt++) {
        int buf = kt & 1;
        if (kt + 1 < KT) ldg(kbeg + (kt + 1) * 16);
        #pragma unroll
        for (int ks = 0; ks < 16; ks += 8) {
            uint32_t af[2][4], bf[4][2];
            #pragma unroll
            for (int i = 0; i < 2; i++) {
                const float* ap = &As[buf][(ks + fq) * ASTR + mb + 16*i + fr];
                af[i][0] = __float_as_uint(ap[0]);
                af[i][1] = __float_as_uint(ap[8]);
                af[i][2] = __float_as_uint(ap[4*ASTR]);
                af[i][3] = __float_as_uint(ap[4*ASTR + 8]);
            }
            #pragma unroll
            for (int j = 0; j < 4; j++) {
                const float* bp = &Bs[buf][(ks + fq) * BSTR + nb + 8*j + fr];
                bf[j][0] = __float_as_uint(bp[0]);
                bf[j][1] = __float_as_uint(bp[4*BSTR]);
            }
            #pragma unroll
            for (int i = 0; i < 2; i++)
                #pragma unroll
                for (int j = 0; j < 4; j++)
                    asm volatile(
                        "mma.sync.aligned.m16n8k8.row.col.f32.tf32.tf32.f32 "
                        "{%0,%1,%2,%3}, {%4,%5,%6,%7}, {%8,%9}, {%0,%1,%2,%3};"
                        : "+f"(acc[i][j][0]), "+f"(acc[i][j][1]),
                          "+f"(acc[i][j][2]), "+f"(acc[i][j][3])
                        : "r"(af[i][0]), "r"(af[i][1]), "r"(af[i][2]), "r"(af[i][3]),
                          "r"(bf[j][0]), "r"(bf[j][1]));
        }
        if (kt + 1 < KT) sts(buf ^ 1);
        __syncthreads();
    }

    if (nz > 1) {
        float* W = work + (size_t)z * M * N;
        #pragma unroll
        for (int i = 0; i < 2; i++) {
            int row = m0 + mb + 16*i + fr;
            #pragma unroll
            for (int j = 0; j < 4; j++) {
                int col = n0 + nb + 8*j + 2*fq;
                float2 v0 = {acc[i][j][0], acc[i][j][1]};
                float2 v1 = {acc[i][j][2], acc[i][j][3]};
                *(float2*)&W[(size_t)row * N + col]       = v0;
                *(float2*)&W[(size_t)(row + 8) * N + col] = v1;
            }
        }
    } else {
        #pragma unroll
        for (int i = 0; i < 2; i++) {
            int row = m0 + mb + 16*i + fr;
            #pragma unroll
            for (int j = 0; j < 4; j++) {
                int col = n0 + nb + 8*j + 2*fq;
                float v[4];
                #pragma unroll
                for (int e = 0; e < 4; e++) v[e] = alpha * acc[i][j][e];
                if (bias) {
                    float b0 = bias[col], b1 = bias[col + 1];
                    v[0] += b0; v[1] += b1; v[2] += b0; v[3] += b1;
                }
                float* c0 = C + (size_t)row * ldc + col;
                float* c1 = C + (size_t)(row + 8) * ldc + col;
                if (beta != 0.f) {
                    v[0] += beta * c0[0]; v[1] += beta * c0[1];
                    v[2] += beta * c1[0]; v[3] += beta * c1[1];
                }
                float2 v0 = {v[0], v[1]}, v1 = {v[2], v[3]};
                *(float2*)c0 = v0; *(float2*)c1 = v1;
            }
        }
    }
}

// ---------------- split-K reduce (float4-vectorized, fused epilogues) ----------------
__global__ void __launch_bounds__(256) reduce_k(
    const float* __restrict__ work, int nz, int MN, int N,
    float alpha, float beta, float* __restrict__ C,
    const float* __restrict__ bias,
    const float* __restrict__ zbuf, float* __restrict__ gl, int mode)
{
    int i4 = blockIdx.x * 256 + threadIdx.x;
    int MN4 = MN >> 2;
    const float4* w4 = (const float4*)work;
    float4 s = {0.f, 0.f, 0.f, 0.f};
    for (int zz = 0; zz < nz; zz++) {
        float4 p = w4[(size_t)zz * MN4 + i4];
        s.x += p.x; s.y += p.y; s.z += p.z; s.w += p.w;
    }
    s.x *= alpha; s.y *= alpha; s.z *= alpha; s.w *= alpha;
    int i = i4 << 2;
    int col = i % N;
    if (mode == 1) {
        float4 b4 = *(const float4*)&bias[col];
        s.x += b4.x; s.y += b4.y; s.z += b4.z; s.w += b4.w;
        *(float4*)&C[i] = s;
        float4 g = {gelu_f(s.x), gelu_f(s.y), gelu_f(s.z), gelu_f(s.w)};
        *(float4*)&gl[i] = g;
    } else if (mode == 2) {
        float4 z4 = *(const float4*)&zbuf[i];
        s.x *= dgelu_f(z4.x); s.y *= dgelu_f(z4.y);
        s.z *= dgelu_f(z4.z); s.w *= dgelu_f(z4.w);
        *(float4*)&C[i] = s;
    } else {
        if (bias) {
            float4 b4 = *(const float4*)&bias[col];
            s.x += b4.x; s.y += b4.y; s.z += b4.z; s.w += b4.w;
        }
        if (beta != 0.f) {
            float4 c4 = *(const float4*)&C[i];
            s.x += beta * c4.x; s.y += beta * c4.y;
            s.z += beta * c4.z; s.w += beta * c4.w;
        }
        *(float4*)&C[i] = s;
    }
}

// ---------------- W2 SGD reduce + fused b2/b1 bias SGD ----------------
// blocks [0, NB_W2): W2 -= LR * sum_z work   (MN = HID_*D_, float4)
// blocks [NB_W2, NB_W2+10): bias updates: c<D_ -> b2 from dh; else b1 from dtH
#define NB_W2 ((HID_*D_)/1024)
__global__ void __launch_bounds__(256) reduce_w2b(
    const float* __restrict__ work, int nz, float* __restrict__ W2,
    const float* __restrict__ dh, const float* __restrict__ dtH,
    float* __restrict__ b2, float* __restrict__ b1)
{
    int blk = blockIdx.x;
    if (blk < NB_W2) {
        int i4 = blk * 256 + threadIdx.x;
        const int MN4 = (HID_*D_) >> 2;
        const float4* w4 = (const float4*)work;
        float4 s = {0.f, 0.f, 0.f, 0.f};
        for (int zz = 0; zz < nz; zz++) {
            float4 p = w4[(size_t)zz * MN4 + i4];
            s.x += p.x; s.y += p.y; s.z += p.z; s.w += p.w;
        }
        int i = i4 << 2;
        float4 c4 = *(const float4*)&W2[i];
        c4.x -= LR_ * s.x; c4.y -= LR_ * s.y;
        c4.z -= LR_ * s.z; c4.w -= LR_ * s.w;
        *(float4*)&W2[i] = c4;
    } else {
        int c = (blk - NB_W2) * 256 + threadIdx.x;   // 0 .. D_+HID_-1
        if (c < D_) {
            float s = 0.f;
            for (int i = 0; i < NT_; i++) s += dh[(size_t)i * D_ + c];
            b2[c] -= LR_ * s;
        } else {
            int c1 = c - D_;
            float s = 0.f;
            for (int i = 0; i < NT_; i++) s += dtH[(size_t)i * HID_ + c1];
            b1[c1] -= LR_ * s;
        }
    }
}

// ---------------- reduce partials + residual + bias, then LayerNorm ----------------
__global__ void __launch_bounds__(256) reduce_ln(
    const float* __restrict__ work, int nz,
    const float* __restrict__ bias, const float* __restrict__ res,
    float* __restrict__ hout,
    const float* __restrict__ ls, const float* __restrict__ lb,
    float* __restrict__ y)
{
    __shared__ float sh[8];
    int row = blockIdx.x, tid = threadIdx.x;
    size_t base = (size_t)row * D_;
    int c = tid * 2;
    float2 v = {0.f, 0.f};
    for (int z = 0; z < nz; z++) {
        float2 p = *(const float2*)&work[(size_t)z * MND_ + base + c];
        v.x += p.x; v.y += p.y;
    }
    float2 b2 = *(const float2*)&bias[c];
    float2 r2 = *(const float2*)&res[base + c];
    v.x += b2.x + r2.x; v.y += b2.y + r2.y;
    *(float2*)&hout[base + c] = v;

    float mean = bsum<8>(v.x + v.y, sh) * (1.f / D_);
    float d0 = v.x - mean, d1 = v.y - mean;
    float var = bsum<8>(d0 * d0 + d1 * d1, sh) * (1.f / D_);
    float rstd = rsqrtf(var + 1e-5f);
    float2 s2 = *(const float2*)&ls[c];
    float2 o2 = *(const float2*)&lb[c];
    float2 out = {d0 * rstd * s2.x + o2.x, d1 * rstd * s2.y + o2.y};
    *(float2*)&y[base + c] = out;
}

// ---------------- fused embed + LN1(layer0) ----------------
__global__ void __launch_bounds__(256) embed_ln(const int* __restrict__ x,
    const float* __restrict__ emb, const float* __restrict__ pos, int off,
    float* __restrict__ h, const float* __restrict__ ls, const float* __restrict__ lb,
    float* __restrict__ y)
{
    __shared__ float sh[8];
    int row = blockIdx.x, tid = threadIdx.x;
    int b = row >> 7, s = row & 127;
    int tok = x[b * T_ + off + s];
    size_t base = (size_t)row * D_;
    int c = tid * 2;
    float2 e2 = *(const float2*)&emb[(size_t)tok * D_ + c];
    float2 p2 = *(const float2*)&pos[s * D_ + c];
    float2 v = {e2.x + p2.x, e2.y + p2.y};
    *(float2*)&h[base + c] = v;

    float mean = bsum<8>(v.x + v.y, sh) * (1.f / D_);
    float d0 = v.x - mean, d1 = v.y - mean;
    float var = bsum<8>(d0 * d0 + d1 * d1, sh) * (1.f / D_);
    float rstd = rsqrtf(var + 1e-5f);
    float2 s2 = *(const float2*)&ls[c];
    float2 o2 = *(const float2*)&lb[c];
    float2 out = {d0 * rstd * s2.x + o2.x, d1 * rstd * s2.y + o2.y};
    *(float2*)&y[base + c] = out;
}

// ---------------- LN backward with fused split-K partial sum ----------------
__global__ void __launch_bounds__(256) ln_bwd_f(const float* __restrict__ x,
    const float* __restrict__ work, int nz, const float* __restrict__ s,
    float* __restrict__ dacc, int accum)
{
    __shared__ float sh[8];
    int row = blockIdx.x, tid = threadIdx.x;
    size_t base = (size_t)row * D_;
    int c = tid * 2;
    float2 dy = {0.f, 0.f};
    for (int z = 0; z < nz; z++) {
        float2 p = *(const float2*)&work[(size_t)z * MND_ + base + c];
        dy.x += p.x; dy.y += p.y;
    }
    float2 xv = *(const float2*)&x[base + c];
    float mean = bsum<8>(xv.x + xv.y, sh) * (1.f / D_);
    float d0 = xv.x - mean, d1 = xv.y - mean;
    float var = bsum<8>(d0 * d0 + d1 * d1, sh) * (1.f / D_);
    float rstd = rsqrtf(var + 1e-5f);
    float xh0 = d0 * rstd, xh1 = d1 * rstd;
    float2 s2 = *(const float2*)&s[c];
    float g0 = s2.x * dy.x, g1 = s2.y * dy.y;
    float t1 = bsum<8>(g0 + g1, sh) * (1.f / D_);
    float t2 = bsum<8>(g0 * xh0 + g1 * xh1, sh) * (1.f / D_);
    float dx0 = rstd * (g0 - t1 - xh0 * t2);
    float dx1 = rstd * (g1 - t1 - xh1 * t2);
    float2* ar = (float2*)&dacc[base + c];
    if (accum) { float2 old = *ar; ar->x = old.x + dx0; ar->y = old.y + dx1; }
    else       { float2 nv = {dx0, dx1}; *ar = nv; }
}

// ---------------- attention forward (256 thr, 4-way parallel AV loop) ----------------
__global__ void __launch_bounds__(256) attn_fwd(const float* __restrict__ qkv,
    float* __restrict__ att, float* __restrict__ obuf)
{
    __shared__ float qs[DH_]; __shared__ float sc[S_]; __shared__ float sh[8];
    __shared__ float part[4][DH_ + 1];
    int qi = blockIdx.x, h = blockIdx.y, b = blockIdx.z, tid = threadIdx.x;
    int row = b * S_ + qi;
    if (tid < DH_) qs[tid] = qkv[(size_t)row * (3*D_) + h * DH_ + tid];
    __syncthreads();
    float sj = -1e30f;
    if (tid <= qi) {
        const float* kp = qkv + (size_t)(b * S_ + tid) * (3*D_) + D_ + h * DH_;
        float a = 0.f;
        #pragma unroll
        for (int d = 0; d < DH_; d++) a += qs[d] * kp[d];
        sj = a * ASC_;
    }
    float mx = bmax<8>(sj, sh);
    float e = (tid <= qi) ? __expf(sj - mx) : 0.f;
    float tot = bsum<8>(e, sh);
    float a = e / tot;
    size_t arow = ((size_t)(b * NH_ + h) * S_ + qi) * S_;
    if (tid < S_) { att[arow + tid] = a; sc[tid] = a; }
    __syncthreads();
    int d = tid & (DH_ - 1), p = tid >> 6;
    float acc = 0.f;
    for (int j = p; j <= qi; j += 4)
        acc += sc[j] * qkv[(size_t)(b * S_ + j) * (3*D_) + 2*D_ + h * DH_ + d];
    part[p][d] = acc;
    __syncthreads();
    if (tid < DH_)
        obuf[(size_t)row * D_ + h * DH_ + tid] =
            (part[0][tid] + part[1][tid]) + (part[2][tid] + part[3][tid]);
}

// ---------------- attention backward 1 (256 thr, fused dob partial-sum) ----------------
__global__ void __launch_bounds__(256) attn_bwd1(const float* __restrict__ qkv,
    const float* __restrict__ att, const float* __restrict__ work, int nz,
    float* __restrict__ dob, float* __restrict__ dsbuf, float* __restrict__ dqkv)
{
    __shared__ float dov[DH_]; __shared__ float sc[S_]; __shared__ float sh[8];
    __shared__ float part[4][DH_ + 1];
    int qi = blockIdx.x, h = blockIdx.y, b = blockIdx.z, tid = threadIdx.x;
    int row = b * S_ + qi;
    if (tid < DH_) {
        size_t wi = (size_t)row * D_ + h * DH_ + tid;
        float s = 0.f;
        for (int z = 0; z < nz; z++) s += work[(size_t)z * MND_ + wi];
        dov[tid] = s;
        dob[wi] = s;
    }
    __syncthreads();
    size_t arow = ((size_t)(b * NH_ + h) * S_ + qi) * S_;
    float a = (tid < S_) ? att[arow + tid] : 0.f;
    float datt = 0.f;
    if (tid <= qi) {
        const float* vp = qkv + (size_t)(b * S_ + tid) * (3*D_) + 2*D_ + h * DH_;
        #pragma unroll
        for (int d = 0; d < DH_; d++) datt += dov[d] * vp[d];
    }
    float tot = bsum<8>(a * datt, sh);
    float ds = a * (datt - tot);
    if (tid < S_) { dsbuf[arow + tid] = ds; sc[tid] = ds; }
    __syncthreads();
    int d = tid & (DH_ - 1), p = tid >> 6;
    float acc = 0.f;
    for (int j = p; j <= qi; j += 4)
        acc += sc[j] * qkv[(size_t)(b * S_ + j) * (3*D_) + D_ + h * DH_ + d];
    part[p][d] = acc;
    __syncthreads();
    if (tid < DH_)
        dqkv[(size_t)row * (3*D_) + h * DH_ + tid] =
            ((part[0][tid] + part[1][tid]) + (part[2][tid] + part[3][tid])) * ASC_;
}

// ---------------- attention backward 2 (256 thr, 4-way parallel q loop) ----------------
__global__ void __launch_bounds__(256) attn_bwd2(const float* __restrict__ qkv,
    const float* __restrict__ att, const float* __restrict__ dob,
    const float* __restrict__ dsbuf, float* __restrict__ dqkv)
{
    __shared__ float pk[4][DH_ + 1], pv[4][DH_ + 1];
    int j = blockIdx.x, h = blockIdx.y, b = blockIdx.z, tid = threadIdx.x;
    int d = tid & (DH_ - 1), p = tid >> 6;
    size_t bh = (size_t)(b * NH_ + h) * S_;
    float dk = 0.f, dv = 0.f;
    for (int q = j + p; q < S_; q += 4) {
        float ds = dsbuf[(bh + q) * S_ + j];
        float a  = att[(bh + q) * S_ + j];
        dk += ds * qkv[(size_t)(b * S_ + q) * (3*D_) + h * DH_ + d];
        dv += a  * dob[(size_t)(b * S_ + q) * D_ + h * DH_ + d];
    }
    pk[p][d] = dk; pv[p][d] = dv;
    __syncthreads();
    if (tid < DH_) {
        float dks = (pk[0][tid] + pk[1][tid]) + (pk[2][tid] + pk[3][tid]);
        float dvs = (pv[0][tid] + pv[1][tid]) + (pv[2][tid] + pv[3][tid]);
        dqkv[(size_t)(b * S_ + j) * (3*D_) + D_   + h * DH_ + tid] = dks * ASC_;
        dqkv[(size_t)(b * S_ + j) * (3*D_) + 2*D_ + h * DH_ + tid] = dvs;
    }
}

// ---------------- fused online softmax stats + dlogits (512 thr, float4) ----------------
__global__ void __launch_bounds__(512) smax_dlog(const float* __restrict__ out,
    const int* __restrict__ x, int off, float* __restrict__ dl)
{
    __shared__ float rm[512], rs[512];
    int i = blockIdx.x, tid = threadIdx.x;
    int b = i >> 7, s = i & 127;
    const float* lp = out + ((size_t)(b * (NCH_*S_) + off + s)) * V_;
    const float4* lp4 = (const float4*)lp;

    float m = -1e30f, sum = 0.f;
    for (int v4 = tid; v4 < V_/4; v4 += 512) {
        float4 q = lp4[v4];
        float vals[4] = {q.x, q.y, q.z, q.w};
        #pragma unroll
        for (int e = 0; e < 4; e++) {
            float v = vals[e];
            if (v > m) { sum *= __expf(m - v); m = v; }
            sum += __expf(v - m);
        }
    }
    rm[tid] = m; rs[tid] = sum; __syncthreads();
    for (int w = 256; w > 0; w >>= 1) {
        if (tid < w) {
            float m1 = rm[tid], m2 = rm[tid + w];
            float M = fmaxf(m1, m2);
            rs[tid] = rs[tid] * __expf(m1 - M) + rs[tid + w] * __expf(m2 - M);
            rm[tid] = M;
        }
        __syncthreads();
    }
    m = rm[0];
    float rinv = __fdividef(1.f, rs[0]);
    const float invNT = 1.f / NT_;
    int tgt = x[b * T_ + off + s + 1];

    float4* dl4 = (float4*)(dl + (size_t)i * V_);
    for (int v4 = tid; v4 < V_/4; v4 += 512) {
        float4 q = lp4[v4];
        int vb = v4 * 4;
        float4 p;
        p.x = (__expf(q.x - m) * rinv - (vb + 0 == tgt ? 1.f : 0.f)) * invNT;
        p.y = (__expf(q.y - m) * rinv - (vb + 1 == tgt ? 1.f : 0.f)) * invNT;
        p.z = (__expf(q.z - m) * rinv - (vb + 2 == tgt ? 1.f : 0.f)) * invNT;
        p.w = (__expf(q.w - m) * rinv - (vb + 3 == tgt ? 1.f : 0.f)) * invNT;
        dl4[v4] = p;
    }
}

// ---------------- segmented param copy (one launch) ----------------
#define NW1_ (L_*D_*HID_)
#define NW2_ (L_*HID_*D_)
#define NB1_ (L_*HID_)
#define NB2_ (L_*D_)
__global__ void __launch_bounds__(256) copy_params(
    const float* __restrict__ w1, const float* __restrict__ w2,
    const float* __restrict__ b1, const float* __restrict__ b2,
    float* __restrict__ pw1, float* __restrict__ pw2,
    float* __restrict__ pb1, float* __restrict__ pb2)
{
    int i = blockIdx.x * 256 + threadIdx.x;
    if (i < NW1_) { pw1[i] = w1[i]; }
    int j = i - NW1_;
    if (j >= 0 && j < NW2_) { pw2[j] = w2[j]; }
    int k = i - NW1_ - NW2_;
    if (k >= 0 && k < NB1_) { pb1[k] = b1[k]; }
    int l = i - NW1_ - NW2_ - NB1_;
    if (l >= 0 && l < NB2_) { pb2[l] = b2[l]; }
}

// ---------------- host ----------------
static float* P(const void* sym) { void* p = 0; cudaGetSymbolAddress(&p, sym); return (float*)p; }

static float* h_work;

static void gemmx(int TA, int TB, int M, int N, int K, int nz, float alpha,
                  const float* A, int lda, const float* B, int ldb,
                  float beta, float* C, int ldc, const float* bias)
{
    dim3 g(N / 64, M / 128, nz);
    if (!TA && !TB)      gemm64<0,0><<<g,256>>>(M,N,K,alpha,A,lda,B,ldb,beta,C,ldc,bias,h_work,0,0,0);
    else if (!TA && TB)  gemm64<0,1><<<g,256>>>(M,N,K,alpha,A,lda,B,ldb,beta,C,ldc,bias,h_work,0,0,0);
    else if (TA && !TB)  gemm64<1,0><<<g,256>>>(M,N,K,alpha,A,lda,B,ldb,beta,C,ldc,bias,h_work,0,0,0);
    else                 gemm64<1,1><<<g,256>>>(M,N,K,alpha,A,lda,B,ldb,beta,C,ldc,bias,h_work,0,0,0);
}

extern "C" void kernel_launch(void* const* d_in, const int* in_sizes, int n_in,
                              void* d_out, int out_size)
{
    const int*   x     = (const int*)  d_in[0];
    const float* emb   = (const float*)d_in[1];
    const float* pos   = (const float*)d_in[2];
    const float* ln1s  = (const float*)d_in[3];
    const float* ln1b  = (const float*)d_in[4];
    const float* Wqkv  = (const float*)d_in[5];
    const float* bqkv  = (const float*)d_in[6];
    const float* Wo    = (const float*)d_in[7];
    const float* bo    = (const float*)d_in[8];
    const float* ln2s  = (const float*)d_in[9];
    const float* ln2b  = (const float*)d_in[10];
    const float* W1i   = (const float*)d_in[11];
    const float* b1i   = (const float*)d_in[12];
    const float* W2i   = (const float*)d_in[13];
    const float* b2i   = (const float*)d_in[14];
    const float* lnfs  = (const float*)d_in[15];
    const float* lnfb  = (const float*)d_in[16];
    const float* Whead = (const float*)d_in[17];
    const float* bhead = (const float*)d_in[18];
    float* out = (float*)d_out;

    float *pW1 = P(g_W1), *pW2 = P(g_W2), *pb1 = P(g_b1), *pb2 = P(g_b2);
    float *ph = P(g_h), *phmid = P(g_hmid), *phfin = P(g_hfin), *pm = P(g_m);
    float *pqkv = P(g_qkv), *patt = P(g_att), *pz1 = P(g_z1), *pgl = P(g_gl);
    float *pabuf = P(g_abuf), *pobuf = P(g_obuf), *pdh = P(g_dh);
    float *pdtH = P(g_dtH), *pdob = P(g_dob);
    float *pdqkv = P(g_dqkv), *pds = P(g_ds), *pdlog = P(g_dlog);
    h_work = P(g_work);

    const int copyN = NW1_ + NW2_ + NB1_ + NB2_;
    copy_params<<<(copyN + 255)/256, 256>>>(W1i, W2i, b1i, b2i, pW1, pW2, pb1, pb2);

    for (int c = 0; c < NCH_; c++) {
        const int off = c * S_;

        // ---------------- forward ----------------
        embed_ln<<<NT_, 256>>>(x, emb, pos, off, ph, ln1s, ln1b, pabuf);
        for (int l = 0; l < L_; l++) {
            float* hin = ph + (size_t)l * ND_;
            float* hmid = phmid + (size_t)l * ND_;
            float* hout = (l < L_-1) ? ph + (size_t)(l+1)*ND_ : phfin;
            const float* nls = (l < L_-1) ? ln1s + (l+1)*D_ : lnfs;
            const float* nlb = (l < L_-1) ? ln1b + (l+1)*D_ : lnfb;

            gemmx(0,0, NT_, 3*D_, D_, 8, 1.f, pabuf, D_, Wqkv + (size_t)l*D_*3*D_, 3*D_, 0.f, 0, 0, 0);
            reduce_k<<<NQ_/1024, 256>>>(h_work, 8, NQ_, 3*D_, 1.f, 0.f,
                                        pqkv + (size_t)l*NQ_, bqkv + l*3*D_, 0, 0, 0);
            attn_fwd<<<dim3(S_,NH_,B_), 256>>>(pqkv + (size_t)l*NQ_, patt + (size_t)l*NA_, pobuf);
            gemmx(0,0, NT_, D_, D_, 16, 1.f, pobuf, D_, Wo + (size_t)l*D_*D_, D_, 0.f, 0, 0, 0);
            reduce_ln<<<NT_, 256>>>(h_work, 16, bo + l*D_, hin, hmid,
                                    ln2s + l*D_, ln2b + l*D_, pm + (size_t)l*ND_);
            gemmx(0,0, NT_, HID_, D_, 4, 1.f, pm + (size_t)l*ND_, D_, pW1 + (size_t)l*D_*HID_, HID_, 0.f, 0, 0, 0);
            reduce_k<<<NH1_/1024, 256>>>(h_work, 4, NH1_, HID_, 1.f, 0.f,
                                         pz1 + (size_t)l*NH1_, pb1 + l*HID_,
                                         0, pgl + (size_t)l*NH1_, 1);
            gemmx(0,0, NT_, D_, HID_, 16, 1.f, pgl + (size_t)l*NH1_, HID_, pW2 + (size_t)l*HID_*D_, D_, 0.f, 0, 0, 0);
            reduce_ln<<<NT_, 256>>>(h_work, 16, pb2 + l*D_, hmid, hout, nls, nlb, pabuf);
        }
        // logits: batched over B via blockIdx.z
        {
            dim3 g(V_ / 64, 1, B_);
            gemm64<0,0><<<g,256>>>(128, V_, D_, 1.f, pabuf, D_, Whead, V_,
                                   0.f, out + (size_t)off * V_, V_, bhead, h_work,
                                   1, (size_t)S_*D_, (size_t)(NCH_*S_)*V_);
        }

        // ---------------- backward ----------------
        smax_dlog<<<NT_, 512>>>(out, x, off, pdlog);
        gemmx(0,1, NT_, D_, V_, 20, 1.f, pdlog, V_, Whead, V_, 0.f, 0, 0, 0);
        ln_bwd_f<<<NT_, 256>>>(phfin, h_work, 20, lnfs, pdh, 0);

        for (int l = L_-1; l >= 0; l--) {
            // dtH = (dh @ W2^T) * dgelu(z1)  (split 4 + reduce mode 2)
            gemmx(0,1, NT_, HID_, D_, 4, 1.f, pdh, D_, pW2 + (size_t)l*HID_*D_, D_, 0.f, 0, 0, 0);
            reduce_k<<<NH1_/1024, 256>>>(h_work, 4, NH1_, HID_, 1.f, 0.f, pdtH, 0,
                                         pz1 + (size_t)l*NH1_, 0, 2);
            // W2 grad partials (split 2), then fused W2 SGD + b2/b1 bias SGD
            gemmx(1,0, HID_, D_, NT_, 2, 1.f, pgl + (size_t)l*NH1_, HID_, pdh, D_, 0.f, 0, 0, 0);
            reduce_w2b<<<NB_W2 + (D_+HID_)/256, 256>>>(h_work, 2, pW2 + (size_t)l*HID_*D_,
                                                       pdh, pdtH, pb2 + l*D_, pb1 + l*HID_);
            // dtD(work) = dtH @ W1^T (pre-update W1), split 16 -> ln2 bwd accumulate
            gemmx(0,1, NT_, D_, HID_, 16, 1.f, pdtH, HID_, pW1 + (size_t)l*D_*HID_, HID_, 0.f, 0, 0, 0);
            ln_bwd_f<<<NT_, 256>>>(phmid + (size_t)l*ND_, h_work, 16, ln2s + l*D_, pdh, 1);
            // W1 -= LR * m^T @ dtH  (split 2 + reduce)
            gemmx(1,0, D_, HID_, NT_, 2, 1.f, pm + (size_t)l*ND_, D_, pdtH, HID_, 0.f, 0, 0, 0);
            reduce_k<<<(D_*HID_)/1024, 256>>>(h_work, 2, D_*HID_, HID_, -LR_, 1.f,
                                              pW1 + (size_t)l*D_*HID_, 0, 0, 0, 0);

            // dob(work) = dh @ Wo^T  (split 16; attn_bwd1 reduces inline)
            gemmx(0,1, NT_, D_, D_, 16, 1.f, pdh, D_, Wo + (size_t)l*D_*D_, D_, 0.f, 0, 0, 0);
            attn_bwd1<<<dim3(S_,NH_,B_), 256>>>(pqkv + (size_t)l*NQ_, patt + (size_t)l*NA_,
                                                h_work, 16, pdob, pds, pdqkv);
            attn_bwd2<<<dim3(S_,NH_,B_), 256>>>(pqkv + (size_t)l*NQ_, patt + (size_t)l*NA_,
                                                pdob, pds, pdqkv);
            // dtD(work) = dqkv @ Wqkv^T, split 8 -> ln1 bwd accumulate
            gemmx(0,1, NT_, D_, 3*D_, 8, 1.f, pdqkv, 3*D_, Wqkv + (size_t)l*D_*3*D_, 3*D_, 0.f, 0, 0, 0);
            ln_bwd_f<<<NT_, 256>>>(ph + (size_t)l*ND_, h_work, 8, ln1s + l*D_, pdh, 1);
        }
    }
    (void)in_sizes; (void)n_in; (void)out_size;
}

// round 15
// speedup vs baseline: 1.1902x; 1.0082x over previous
#include <cuda_runtime.h>
#include <math.h>
#include <stdint.h>

#define D_    512
#define HID_  2048
#define L_    4
#define V_    32000
#define B_    2
#define T_    1025
#define S_    128
#define NH_   8
#define DH_   64
#define NT_   256
#define NCH_  8
#define LR_   0.0003f
#define ASC_  0.125f

#define ND_  (NT_*D_)
#define NH1_ (NT_*HID_)
#define NQ_  (NT_*3*D_)
#define NA_  (B_*NH_*S_*S_)
#define MND_ 131072           // 256*512

// ---------------- device scratch ----------------
__device__ float g_W1[L_*D_*HID_];
__device__ float g_W2[L_*HID_*D_];
__device__ float g_b1[L_*HID_];
__device__ float g_b2[L_*D_];
__device__ float g_h[L_*ND_];
__device__ float g_hmid[L_*ND_];
__device__ float g_hfin[ND_];
__device__ float g_m[L_*ND_];
__device__ float g_qkv[L_*NQ_];
__device__ float g_att[L_*NA_];
__device__ float g_z1[L_*NH1_];
__device__ float g_gl[L_*NH1_];
__device__ float g_abuf[ND_];
__device__ float g_obuf[ND_];
__device__ float g_dh[ND_];
__device__ float g_dtH[NH1_];
__device__ float g_dob[ND_];
__device__ float g_dqkv[NQ_];
__device__ float g_ds[NA_];
__device__ float g_dlog[NT_*V_];
__device__ float g_work[8*1024*1024];     // split-K partials (32 MB)

// ---------------- fast-math helpers ----------------
__device__ __forceinline__ float ftanh_(float u) {
    u = fminf(fmaxf(u, -15.f), 15.f);
    float e = __expf(2.f * u);
    return __fdividef(e - 1.f, e + 1.f);
}
__device__ __forceinline__ float gelu_f(float x) {
    float u = 0.7978845608028654f * (x + 0.044715f * x * x * x);
    return 0.5f * x * (1.f + ftanh_(u));
}
__device__ __forceinline__ float dgelu_f(float x) {
    float x2 = x * x;
    float u = 0.7978845608028654f * (x + 0.044715f * x * x2);
    float t = ftanh_(u);
    return 0.5f * (1.f + t)
         + 0.5f * x * (1.f - t * t) * 0.7978845608028654f * (1.f + 3.f * 0.044715f * x2);
}
__device__ __forceinline__ float f2tf_f(float f) {
    uint32_t u;
    asm("cvt.rna.tf32.f32 %0, %1;" : "=r"(u) : "f"(f));
    return __uint_as_float(u);
}

// ---------------- two-level block reductions (2 syncs each) ----------------
template<int NW>
__device__ __forceinline__ float bsum(float v, volatile float* sh) {
    #pragma unroll
    for (int o = 16; o; o >>= 1) v += __shfl_down_sync(0xffffffffu, v, o);
    if ((threadIdx.x & 31) == 0) sh[threadIdx.x >> 5] = v;
    __syncthreads();
    float r = sh[0];
    #pragma unroll
    for (int k = 1; k < NW; k++) r += sh[k];
    __syncthreads();
    return r;
}
template<int NW>
__device__ __forceinline__ float bmax(float v, volatile float* sh) {
    #pragma unroll
    for (int o = 16; o; o >>= 1) v = fmaxf(v, __shfl_down_sync(0xffffffffu, v, o));
    if ((threadIdx.x & 31) == 0) sh[threadIdx.x >> 5] = v;
    __syncthreads();
    float r = sh[0];
    #pragma unroll
    for (int k = 1; k < NW; k++) r = fmaxf(r, sh[k]);
    __syncthreads();
    return r;
}

// ---------------- 128x64x16 tf32 tensor-core GEMM (2 CTAs/SM) ----------------
#define ASTR 136
#define BSTR 72
template<int TA, int TB>
__global__ void __launch_bounds__(256) gemm64(
    int M, int N, int K, float alpha,
    const float* __restrict__ A, int lda,
    const float* __restrict__ B, int ldb,
    float beta, float* __restrict__ C, int ldc,
    const float* __restrict__ bias, float* __restrict__ work,
    int batched, size_t sAz, size_t sCz)
{
    __shared__ __align__(16) float As[2][16*ASTR];
    __shared__ __align__(16) float Bs[2][16*BSTR];
    const int tid = threadIdx.x;
    const int m0 = blockIdx.y * 128, n0 = blockIdx.x * 64;
    const int z = blockIdx.z;
    const int nz = batched ? 1 : gridDim.z;
    const int kslice = batched ? K : (K / gridDim.z);
    const int kbeg = batched ? 0 : z * kslice;
    if (batched) { A += (size_t)z * sAz; C += (size_t)z * sCz; }

    const int a_r = TA ? (tid >> 4) : (tid >> 1);
    const int a_c = TA ? ((tid & 15) * 8) : ((tid & 1) * 8);
    const int b_r = TB ? (tid >> 2) : (tid >> 4);
    const int b_c = TB ? ((tid & 3) * 4) : ((tid & 15) * 4);

    float4 pa0, pa1, pb0;

    auto ldg = [&](int kk) {
        const float* pa = TA ? (A + (size_t)(kk + a_r) * lda + m0 + a_c)
                             : (A + (size_t)(m0 + a_r) * lda + kk + a_c);
        pa0 = *(const float4*)pa; pa1 = *(const float4*)(pa + 4);
        const float* pb = TB ? (B + (size_t)(n0 + b_r) * ldb + kk + b_c)
                             : (B + (size_t)(kk + b_r) * ldb + n0 + b_c);
        pb0 = *(const float4*)pb;
    };
    auto sts = [&](int buf) {
        float va[8] = {pa0.x,pa0.y,pa0.z,pa0.w,pa1.x,pa1.y,pa1.z,pa1.w};
        float vb[4] = {pb0.x,pb0.y,pb0.z,pb0.w};
        #pragma unroll
        for (int i = 0; i < 8; i++) va[i] = f2tf_f(va[i]);
        #pragma unroll
        for (int i = 0; i < 4; i++) vb[i] = f2tf_f(vb[i]);
        if (!TA) {
            #pragma unroll
            for (int i = 0; i < 8; i++) As[buf][(a_c + i) * ASTR + a_r] = va[i];
        } else {
            float4 w0 = {va[0],va[1],va[2],va[3]}, w1 = {va[4],va[5],va[6],va[7]};
            *(float4*)&As[buf][a_r * ASTR + a_c]     = w0;
            *(float4*)&As[buf][a_r * ASTR + a_c + 4] = w1;
        }
        if (!TB) {
            float4 w0 = {vb[0],vb[1],vb[2],vb[3]};
            *(float4*)&Bs[buf][b_r * BSTR + b_c] = w0;
        } else {
            #pragma unroll
            for (int i = 0; i < 4; i++) Bs[buf][(b_c + i) * BSTR + b_r] = vb[i];
        }
    };

    const int warp = tid >> 5, lane = tid & 31;
    const int mb = (warp >> 1) * 32;
    const int nb = (warp & 1) * 32;
    const int fr = lane >> 2, fq = lane & 3;

    float acc[2][4][4];
    #pragma unroll
    for (int i = 0; i < 2; i++)
        #pragma unroll
        for (int j = 0; j < 4; j++)
            #pragma unroll
            for (int e = 0; e < 4; e++) acc[i][j][e] = 0.f;

    ldg(kbeg); sts(0); __syncthreads();
    const int KT = kslice >> 4;
    for (int kt = 0; kt < KT; kt++) {
        int buf = kt & 1;
        if (kt + 1 < KT) ldg(kbeg + (kt + 1) * 16);
        #pragma unroll
        for (int ks = 0; ks < 16; ks += 8) {
            uint32_t af[2][4], bf[4][2];
            #pragma unroll
            for (int i = 0; i < 2; i++) {
                const float* ap = &As[buf][(ks + fq) * ASTR + mb + 16*i + fr];
                af[i][0] = __float_as_uint(ap[0]);
                af[i][1] = __float_as_uint(ap[8]);
                af[i][2] = __float_as_uint(ap[4*ASTR]);
                af[i][3] = __float_as_uint(ap[4*ASTR + 8]);
            }
            #pragma unroll
            for (int j = 0; j < 4; j++) {
                const float* bp = &Bs[buf][(ks + fq) * BSTR + nb + 8*j + fr];
                bf[j][0] = __float_as_uint(bp[0]);
                bf[j][1] = __float_as_uint(bp[4*BSTR]);
            }
            #pragma unroll
            for (int i = 0; i < 2; i++)
                #pragma unroll
                for (int j = 0; j < 4; j++)
                    asm volatile(
                        "mma.sync.aligned.m16n8k8.row.col.f32.tf32.tf32.f32 "
                        "{%0,%1,%2,%3}, {%4,%5,%6,%7}, {%8,%9}, {%0,%1,%2,%3};"
                        : "+f"(acc[i][j][0]), "+f"(acc[i][j][1]),
                          "+f"(acc[i][j][2]), "+f"(acc[i][j][3])
                        : "r"(af[i][0]), "r"(af[i][1]), "r"(af[i][2]), "r"(af[i][3]),
                          "r"(bf[j][0]), "r"(bf[j][1]));
        }
        if (kt + 1 < KT) sts(buf ^ 1);
        __syncthreads();
    }

    if (nz > 1) {
        float* W = work + (size_t)z * M * N;
        #pragma unroll
        for (int i = 0; i < 2; i++) {
            int row = m0 + mb + 16*i + fr;
            #pragma unroll
            for (int j = 0; j < 4; j++) {
                int col = n0 + nb + 8*j + 2*fq;
                float2 v0 = {acc[i][j][0], acc[i][j][1]};
                float2 v1 = {acc[i][j][2], acc[i][j][3]};
                *(float2*)&W[(size_t)row * N + col]       = v0;
                *(float2*)&W[(size_t)(row + 8) * N + col] = v1;
            }
        }
    } else {
        #pragma unroll
        for (int i = 0; i < 2; i++) {
            int row = m0 + mb + 16*i + fr;
            #pragma unroll
            for (int j = 0; j < 4; j++) {
                int col = n0 + nb + 8*j + 2*fq;
                float v[4];
                #pragma unroll
                for (int e = 0; e < 4; e++) v[e] = alpha * acc[i][j][e];
                if (bias) {
                    float b0 = bias[col], b1 = bias[col + 1];
                    v[0] += b0; v[1] += b1; v[2] += b0; v[3] += b1;
                }
                float* c0 = C + (size_t)row * ldc + col;
                float* c1 = C + (size_t)(row + 8) * ldc + col;
                if (beta != 0.f) {
                    v[0] += beta * c0[0]; v[1] += beta * c0[1];
                    v[2] += beta * c1[0]; v[3] += beta * c1[1];
                }
                float2 v0 = {v[0], v[1]}, v1 = {v[2], v[3]};
                *(float2*)c0 = v0; *(float2*)c1 = v1;
            }
        }
    }
}

// ---------------- split-K reduce (float4-vectorized, fused epilogues) ----------------
__global__ void __launch_bounds__(256) reduce_k(
    const float* __restrict__ work, int nz, int MN, int N,
    float alpha, float beta, float* __restrict__ C,
    const float* __restrict__ bias,
    const float* __restrict__ zbuf, float* __restrict__ gl, int mode)
{
    int i4 = blockIdx.x * 256 + threadIdx.x;
    int MN4 = MN >> 2;
    const float4* w4 = (const float4*)work;
    float4 s = {0.f, 0.f, 0.f, 0.f};
    for (int zz = 0; zz < nz; zz++) {
        float4 p = w4[(size_t)zz * MN4 + i4];
        s.x += p.x; s.y += p.y; s.z += p.z; s.w += p.w;
    }
    s.x *= alpha; s.y *= alpha; s.z *= alpha; s.w *= alpha;
    int i = i4 << 2;
    int col = i % N;
    if (mode == 1) {
        float4 b4 = *(const float4*)&bias[col];
        s.x += b4.x; s.y += b4.y; s.z += b4.z; s.w += b4.w;
        *(float4*)&C[i] = s;
        float4 g = {gelu_f(s.x), gelu_f(s.y), gelu_f(s.z), gelu_f(s.w)};
        *(float4*)&gl[i] = g;
    } else if (mode == 2) {
        float4 z4 = *(const float4*)&zbuf[i];
        s.x *= dgelu_f(z4.x); s.y *= dgelu_f(z4.y);
        s.z *= dgelu_f(z4.z); s.w *= dgelu_f(z4.w);
        *(float4*)&C[i] = s;
    } else {
        if (bias) {
            float4 b4 = *(const float4*)&bias[col];
            s.x += b4.x; s.y += b4.y; s.z += b4.z; s.w += b4.w;
        }
        if (beta != 0.f) {
            float4 c4 = *(const float4*)&C[i];
            s.x += beta * c4.x; s.y += beta * c4.y;
            s.z += beta * c4.z; s.w += beta * c4.w;
        }
        *(float4*)&C[i] = s;
    }
}

// ---------------- W2 SGD reduce + fused b2/b1 bias SGD ----------------
#define NB_W2 ((HID_*D_)/1024)
__global__ void __launch_bounds__(256) reduce_w2b(
    const float* __restrict__ work, int nz, float* __restrict__ W2,
    const float* __restrict__ dh, const float* __restrict__ dtH,
    float* __restrict__ b2, float* __restrict__ b1)
{
    int blk = blockIdx.x;
    if (blk < NB_W2) {
        int i4 = blk * 256 + threadIdx.x;
        const int MN4 = (HID_*D_) >> 2;
        const float4* w4 = (const float4*)work;
        float4 s = {0.f, 0.f, 0.f, 0.f};
        for (int zz = 0; zz < nz; zz++) {
            float4 p = w4[(size_t)zz * MN4 + i4];
            s.x += p.x; s.y += p.y; s.z += p.z; s.w += p.w;
        }
        int i = i4 << 2;
        float4 c4 = *(const float4*)&W2[i];
        c4.x -= LR_ * s.x; c4.y -= LR_ * s.y;
        c4.z -= LR_ * s.z; c4.w -= LR_ * s.w;
        *(float4*)&W2[i] = c4;
    } else {
        int c = (blk - NB_W2) * 256 + threadIdx.x;
        if (c < D_) {
            float s = 0.f;
            for (int i = 0; i < NT_; i++) s += dh[(size_t)i * D_ + c];
            b2[c] -= LR_ * s;
        } else {
            int c1 = c - D_;
            float s = 0.f;
            for (int i = 0; i < NT_; i++) s += dtH[(size_t)i * HID_ + c1];
            b1[c1] -= LR_ * s;
        }
    }
}

// ---------------- reduce partials + residual + bias, then LayerNorm ----------------
__global__ void __launch_bounds__(256) reduce_ln(
    const float* __restrict__ work, int nz,
    const float* __restrict__ bias, const float* __restrict__ res,
    float* __restrict__ hout,
    const float* __restrict__ ls, const float* __restrict__ lb,
    float* __restrict__ y)
{
    __shared__ float sh[8];
    int row = blockIdx.x, tid = threadIdx.x;
    size_t base = (size_t)row * D_;
    int c = tid * 2;
    float2 v = {0.f, 0.f};
    for (int z = 0; z < nz; z++) {
        float2 p = *(const float2*)&work[(size_t)z * MND_ + base + c];
        v.x += p.x; v.y += p.y;
    }
    float2 b2 = *(const float2*)&bias[c];
    float2 r2 = *(const float2*)&res[base + c];
    v.x += b2.x + r2.x; v.y += b2.y + r2.y;
    *(float2*)&hout[base + c] = v;

    float mean = bsum<8>(v.x + v.y, sh) * (1.f / D_);
    float d0 = v.x - mean, d1 = v.y - mean;
    float var = bsum<8>(d0 * d0 + d1 * d1, sh) * (1.f / D_);
    float rstd = rsqrtf(var + 1e-5f);
    float2 s2 = *(const float2*)&ls[c];
    float2 o2 = *(const float2*)&lb[c];
    float2 out = {d0 * rstd * s2.x + o2.x, d1 * rstd * s2.y + o2.y};
    *(float2*)&y[base + c] = out;
}

// ---------------- fused embed + LN1(layer0) ----------------
__global__ void __launch_bounds__(256) embed_ln(const int* __restrict__ x,
    const float* __restrict__ emb, const float* __restrict__ pos, int off,
    float* __restrict__ h, const float* __restrict__ ls, const float* __restrict__ lb,
    float* __restrict__ y)
{
    __shared__ float sh[8];
    int row = blockIdx.x, tid = threadIdx.x;
    int b = row >> 7, s = row & 127;
    int tok = x[b * T_ + off + s];
    size_t base = (size_t)row * D_;
    int c = tid * 2;
    float2 e2 = *(const float2*)&emb[(size_t)tok * D_ + c];
    float2 p2 = *(const float2*)&pos[s * D_ + c];
    float2 v = {e2.x + p2.x, e2.y + p2.y};
    *(float2*)&h[base + c] = v;

    float mean = bsum<8>(v.x + v.y, sh) * (1.f / D_);
    float d0 = v.x - mean, d1 = v.y - mean;
    float var = bsum<8>(d0 * d0 + d1 * d1, sh) * (1.f / D_);
    float rstd = rsqrtf(var + 1e-5f);
    float2 s2 = *(const float2*)&ls[c];
    float2 o2 = *(const float2*)&lb[c];
    float2 out = {d0 * rstd * s2.x + o2.x, d1 * rstd * s2.y + o2.y};
    *(float2*)&y[base + c] = out;
}

// ---------------- LN backward with fused split-K partial sum ----------------
__global__ void __launch_bounds__(256) ln_bwd_f(const float* __restrict__ x,
    const float* __restrict__ work, int nz, const float* __restrict__ s,
    float* __restrict__ dacc, int accum)
{
    __shared__ float sh[8];
    int row = blockIdx.x, tid = threadIdx.x;
    size_t base = (size_t)row * D_;
    int c = tid * 2;
    float2 dy = {0.f, 0.f};
    for (int z = 0; z < nz; z++) {
        float2 p = *(const float2*)&work[(size_t)z * MND_ + base + c];
        dy.x += p.x; dy.y += p.y;
    }
    float2 xv = *(const float2*)&x[base + c];
    float mean = bsum<8>(xv.x + xv.y, sh) * (1.f / D_);
    float d0 = xv.x - mean, d1 = xv.y - mean;
    float var = bsum<8>(d0 * d0 + d1 * d1, sh) * (1.f / D_);
    float rstd = rsqrtf(var + 1e-5f);
    float xh0 = d0 * rstd, xh1 = d1 * rstd;
    float2 s2 = *(const float2*)&s[c];
    float g0 = s2.x * dy.x, g1 = s2.y * dy.y;
    float t1 = bsum<8>(g0 + g1, sh) * (1.f / D_);
    float t2 = bsum<8>(g0 * xh0 + g1 * xh1, sh) * (1.f / D_);
    float dx0 = rstd * (g0 - t1 - xh0 * t2);
    float dx1 = rstd * (g1 - t1 - xh1 * t2);
    float2* ar = (float2*)&dacc[base + c];
    if (accum) { float2 old = *ar; ar->x = old.x + dx0; ar->y = old.y + dx1; }
    else       { float2 nv = {dx0, dx1}; *ar = nv; }
}

// ---------------- attention forward (256 thr, 4-way parallel AV loop) ----------------
__global__ void __launch_bounds__(256) attn_fwd(const float* __restrict__ qkv,
    float* __restrict__ att, float* __restrict__ obuf)
{
    __shared__ float qs[DH_]; __shared__ float sc[S_]; __shared__ float sh[8];
    __shared__ float part[4][DH_ + 1];
    int qi = blockIdx.x, h = blockIdx.y, b = blockIdx.z, tid = threadIdx.x;
    int row = b * S_ + qi;
    if (tid < DH_) qs[tid] = qkv[(size_t)row * (3*D_) + h * DH_ + tid];
    __syncthreads();
    float sj = -1e30f;
    if (tid <= qi) {
        const float* kp = qkv + (size_t)(b * S_ + tid) * (3*D_) + D_ + h * DH_;
        float a = 0.f;
        #pragma unroll
        for (int d = 0; d < DH_; d++) a += qs[d] * kp[d];
        sj = a * ASC_;
    }
    float mx = bmax<8>(sj, sh);
    float e = (tid <= qi) ? __expf(sj - mx) : 0.f;
    float tot = bsum<8>(e, sh);
    float a = e / tot;
    size_t arow = ((size_t)(b * NH_ + h) * S_ + qi) * S_;
    if (tid < S_) { att[arow + tid] = a; sc[tid] = a; }
    __syncthreads();
    int d = tid & (DH_ - 1), p = tid >> 6;
    float acc = 0.f;
    for (int j = p; j <= qi; j += 4)
        acc += sc[j] * qkv[(size_t)(b * S_ + j) * (3*D_) + 2*D_ + h * DH_ + d];
    part[p][d] = acc;
    __syncthreads();
    if (tid < DH_)
        obuf[(size_t)row * D_ + h * DH_ + tid] =
            (part[0][tid] + part[1][tid]) + (part[2][tid] + part[3][tid]);
}

// ---------------- attention backward 1 (256 thr, fused dob partial-sum) ----------------
__global__ void __launch_bounds__(256) attn_bwd1(const float* __restrict__ qkv,
    const float* __restrict__ att, const float* __restrict__ work, int nz,
    float* __restrict__ dob, float* __restrict__ dsbuf, float* __restrict__ dqkv)
{
    __shared__ float dov[DH_]; __shared__ float sc[S_]; __shared__ float sh[8];
    __shared__ float part[4][DH_ + 1];
    int qi = blockIdx.x, h = blockIdx.y, b = blockIdx.z, tid = threadIdx.x;
    int row = b * S_ + qi;
    if (tid < DH_) {
        size_t wi = (size_t)row * D_ + h * DH_ + tid;
        float s = 0.f;
        for (int z = 0; z < nz; z++) s += work[(size_t)z * MND_ + wi];
        dov[tid] = s;
        dob[wi] = s;
    }
    __syncthreads();
    size_t arow = ((size_t)(b * NH_ + h) * S_ + qi) * S_;
    float a = (tid < S_) ? att[arow + tid] : 0.f;
    float datt = 0.f;
    if (tid <= qi) {
        const float* vp = qkv + (size_t)(b * S_ + tid) * (3*D_) + 2*D_ + h * DH_;
        #pragma unroll
        for (int d = 0; d < DH_; d++) datt += dov[d] * vp[d];
    }
    float tot = bsum<8>(a * datt, sh);
    float ds = a * (datt - tot);
    if (tid < S_) { dsbuf[arow + tid] = ds; sc[tid] = ds; }
    __syncthreads();
    int d = tid & (DH_ - 1), p = tid >> 6;
    float acc = 0.f;
    for (int j = p; j <= qi; j += 4)
        acc += sc[j] * qkv[(size_t)(b * S_ + j) * (3*D_) + D_ + h * DH_ + d];
    part[p][d] = acc;
    __syncthreads();
    if (tid < DH_)
        dqkv[(size_t)row * (3*D_) + h * DH_ + tid] =
            ((part[0][tid] + part[1][tid]) + (part[2][tid] + part[3][tid])) * ASC_;
}

// ---------------- attention backward 2 (256 thr, 4-way parallel q loop) ----------------
__global__ void __launch_bounds__(256) attn_bwd2(const float* __restrict__ qkv,
    const float* __restrict__ att, const float* __restrict__ dob,
    const float* __restrict__ dsbuf, float* __restrict__ dqkv)
{
    __shared__ float pk[4][DH_ + 1], pv[4][DH_ + 1];
    int j = blockIdx.x, h = blockIdx.y, b = blockIdx.z, tid = threadIdx.x;
    int d = tid & (DH_ - 1), p = tid >> 6;
    size_t bh = (size_t)(b * NH_ + h) * S_;
    float dk = 0.f, dv = 0.f;
    for (int q = j + p; q < S_; q += 4) {
        float ds = dsbuf[(bh + q) * S_ + j];
        float a  = att[(bh + q) * S_ + j];
        dk += ds * qkv[(size_t)(b * S_ + q) * (3*D_) + h * DH_ + d];
        dv += a  * dob[(size_t)(b * S_ + q) * D_ + h * DH_ + d];
    }
    pk[p][d] = dk; pv[p][d] = dv;
    __syncthreads();
    if (tid < DH_) {
        float dks = (pk[0][tid] + pk[1][tid]) + (pk[2][tid] + pk[3][tid]);
        float dvs = (pv[0][tid] + pv[1][tid]) + (pv[2][tid] + pv[3][tid]);
        dqkv[(size_t)(b * S_ + j) * (3*D_) + D_   + h * DH_ + tid] = dks * ASC_;
        dqkv[(size_t)(b * S_ + j) * (3*D_) + 2*D_ + h * DH_ + tid] = dvs;
    }
}

// ---------------- softmax + dlogits: single exp pass, cached in dlog ----------------
// Whead is never trained -> logits stay O(1); shift-free softmax is safe in fp32.
// Pass A: e = exp(v) stored to dlog, block-reduce sum.
// Pass B: dlog = e*rinv - onehot, scaled by 1/NT.
__global__ void __launch_bounds__(512) smax_dlog(const float* __restrict__ out,
    const int* __restrict__ x, int off, float* __restrict__ dl)
{
    __shared__ float rs[512];
    int i = blockIdx.x, tid = threadIdx.x;
    int b = i >> 7, s = i & 127;
    const float4* lp4 = (const float4*)(out + ((size_t)(b * (NCH_*S_) + off + s)) * V_);
    float4* dl4 = (float4*)(dl + (size_t)i * V_);

    float sum = 0.f;
    for (int v4 = tid; v4 < V_/4; v4 += 512) {
        float4 q = lp4[v4];
        float4 e;
        e.x = __expf(q.x); e.y = __expf(q.y);
        e.z = __expf(q.z); e.w = __expf(q.w);
        sum += (e.x + e.y) + (e.z + e.w);
        dl4[v4] = e;
    }
    rs[tid] = sum; __syncthreads();
    for (int w = 256; w > 0; w >>= 1) {
        if (tid < w) rs[tid] += rs[tid + w];
        __syncthreads();
    }
    float rinv = __fdividef(1.f, rs[0]);
    const float invNT = 1.f / NT_;
    int tgt = x[b * T_ + off + s + 1];

    for (int v4 = tid; v4 < V_/4; v4 += 512) {
        float4 e = dl4[v4];
        int vb = v4 * 4;
        float4 p;
        p.x = (e.x * rinv - (vb + 0 == tgt ? 1.f : 0.f)) * invNT;
        p.y = (e.y * rinv - (vb + 1 == tgt ? 1.f : 0.f)) * invNT;
        p.z = (e.z * rinv - (vb + 2 == tgt ? 1.f : 0.f)) * invNT;
        p.w = (e.w * rinv - (vb + 3 == tgt ? 1.f : 0.f)) * invNT;
        dl4[v4] = p;
    }
}

// ---------------- segmented param copy (one launch) ----------------
#define NW1_ (L_*D_*HID_)
#define NW2_ (L_*HID_*D_)
#define NB1_ (L_*HID_)
#define NB2_ (L_*D_)
__global__ void __launch_bounds__(256) copy_params(
    const float* __restrict__ w1, const float* __restrict__ w2,
    const float* __restrict__ b1, const float* __restrict__ b2,
    float* __restrict__ pw1, float* __restrict__ pw2,
    float* __restrict__ pb1, float* __restrict__ pb2)
{
    int i = blockIdx.x * 256 + threadIdx.x;
    if (i < NW1_) { pw1[i] = w1[i]; }
    int j = i - NW1_;
    if (j >= 0 && j < NW2_) { pw2[j] = w2[j]; }
    int k = i - NW1_ - NW2_;
    if (k >= 0 && k < NB1_) { pb1[k] = b1[k]; }
    int l = i - NW1_ - NW2_ - NB1_;
    if (l >= 0 && l < NB2_) { pb2[l] = b2[l]; }
}

// ---------------- host ----------------
static float* P(const void* sym) { void* p = 0; cudaGetSymbolAddress(&p, sym); return (float*)p; }

static float* h_work;

static void gemmx(int TA, int TB, int M, int N, int K, int nz, float alpha,
                  const float* A, int lda, const float* B, int ldb,
                  float beta, float* C, int ldc, const float* bias)
{
    dim3 g(N / 64, M / 128, nz);
    if (!TA && !TB)      gemm64<0,0><<<g,256>>>(M,N,K,alpha,A,lda,B,ldb,beta,C,ldc,bias,h_work,0,0,0);
    else if (!TA && TB)  gemm64<0,1><<<g,256>>>(M,N,K,alpha,A,lda,B,ldb,beta,C,ldc,bias,h_work,0,0,0);
    else if (TA && !TB)  gemm64<1,0><<<g,256>>>(M,N,K,alpha,A,lda,B,ldb,beta,C,ldc,bias,h_work,0,0,0);
    else                 gemm64<1,1><<<g,256>>>(M,N,K,alpha,A,lda,B,ldb,beta,C,ldc,bias,h_work,0,0,0);
}

extern "C" void kernel_launch(void* const* d_in, const int* in_sizes, int n_in,
                              void* d_out, int out_size)
{
    const int*   x     = (const int*)  d_in[0];
    const float* emb   = (const float*)d_in[1];
    const float* pos   = (const float*)d_in[2];
    const float* ln1s  = (const float*)d_in[3];
    const float* ln1b  = (const float*)d_in[4];
    const float* Wqkv  = (const float*)d_in[5];
    const float* bqkv  = (const float*)d_in[6];
    const float* Wo    = (const float*)d_in[7];
    const float* bo    = (const float*)d_in[8];
    const float* ln2s  = (const float*)d_in[9];
    const float* ln2b  = (const float*)d_in[10];
    const float* W1i   = (const float*)d_in[11];
    const float* b1i   = (const float*)d_in[12];
    const float* W2i   = (const float*)d_in[13];
    const float* b2i   = (const float*)d_in[14];
    const float* lnfs  = (const float*)d_in[15];
    const float* lnfb  = (const float*)d_in[16];
    const float* Whead = (const float*)d_in[17];
    const float* bhead = (const float*)d_in[18];
    float* out = (float*)d_out;

    float *pW1 = P(g_W1), *pW2 = P(g_W2), *pb1 = P(g_b1), *pb2 = P(g_b2);
    float *ph = P(g_h), *phmid = P(g_hmid), *phfin = P(g_hfin), *pm = P(g_m);
    float *pqkv = P(g_qkv), *patt = P(g_att), *pz1 = P(g_z1), *pgl = P(g_gl);
    float *pabuf = P(g_abuf), *pobuf = P(g_obuf), *pdh = P(g_dh);
    float *pdtH = P(g_dtH), *pdob = P(g_dob);
    float *pdqkv = P(g_dqkv), *pds = P(g_ds), *pdlog = P(g_dlog);
    h_work = P(g_work);

    const int copyN = NW1_ + NW2_ + NB1_ + NB2_;
    copy_params<<<(copyN + 255)/256, 256>>>(W1i, W2i, b1i, b2i, pW1, pW2, pb1, pb2);

    for (int c = 0; c < NCH_; c++) {
        const int off = c * S_;

        // ---------------- forward ----------------
        embed_ln<<<NT_, 256>>>(x, emb, pos, off, ph, ln1s, ln1b, pabuf);
        for (int l = 0; l < L_; l++) {
            float* hin = ph + (size_t)l * ND_;
            float* hmid = phmid + (size_t)l * ND_;
            float* hout = (l < L_-1) ? ph + (size_t)(l+1)*ND_ : phfin;
            const float* nls = (l < L_-1) ? ln1s + (l+1)*D_ : lnfs;
            const float* nlb = (l < L_-1) ? ln1b + (l+1)*D_ : lnfb;

            gemmx(0,0, NT_, 3*D_, D_, 8, 1.f, pabuf, D_, Wqkv + (size_t)l*D_*3*D_, 3*D_, 0.f, 0, 0, 0);
            reduce_k<<<NQ_/1024, 256>>>(h_work, 8, NQ_, 3*D_, 1.f, 0.f,
                                        pqkv + (size_t)l*NQ_, bqkv + l*3*D_, 0, 0, 0);
            attn_fwd<<<dim3(S_,NH_,B_), 256>>>(pqkv + (size_t)l*NQ_, patt + (size_t)l*NA_, pobuf);
            gemmx(0,0, NT_, D_, D_, 16, 1.f, pobuf, D_, Wo + (size_t)l*D_*D_, D_, 0.f, 0, 0, 0);
            reduce_ln<<<NT_, 256>>>(h_work, 16, bo + l*D_, hin, hmid,
                                    ln2s + l*D_, ln2b + l*D_, pm + (size_t)l*ND_);
            gemmx(0,0, NT_, HID_, D_, 4, 1.f, pm + (size_t)l*ND_, D_, pW1 + (size_t)l*D_*HID_, HID_, 0.f, 0, 0, 0);
            reduce_k<<<NH1_/1024, 256>>>(h_work, 4, NH1_, HID_, 1.f, 0.f,
                                         pz1 + (size_t)l*NH1_, pb1 + l*HID_,
                                         0, pgl + (size_t)l*NH1_, 1);
            gemmx(0,0, NT_, D_, HID_, 16, 1.f, pgl + (size_t)l*NH1_, HID_, pW2 + (size_t)l*HID_*D_, D_, 0.f, 0, 0, 0);
            reduce_ln<<<NT_, 256>>>(h_work, 16, pb2 + l*D_, hmid, hout, nls, nlb, pabuf);
        }
        // logits: batched over B via blockIdx.z
        {
            dim3 g(V_ / 64, 1, B_);
            gemm64<0,0><<<g,256>>>(128, V_, D_, 1.f, pabuf, D_, Whead, V_,
                                   0.f, out + (size_t)off * V_, V_, bhead, h_work,
                                   1, (size_t)S_*D_, (size_t)(NCH_*S_)*V_);
        }

        // ---------------- backward ----------------
        smax_dlog<<<NT_, 512>>>(out, x, off, pdlog);
        gemmx(0,1, NT_, D_, V_, 16, 1.f, pdlog, V_, Whead, V_, 0.f, 0, 0, 0);
        ln_bwd_f<<<NT_, 256>>>(phfin, h_work, 16, lnfs, pdh, 0);

        for (int l = L_-1; l >= 0; l--) {
            // dtH = (dh @ W2^T) * dgelu(z1)  (split 4 + reduce mode 2)
            gemmx(0,1, NT_, HID_, D_, 4, 1.f, pdh, D_, pW2 + (size_t)l*HID_*D_, D_, 0.f, 0, 0, 0);
            reduce_k<<<NH1_/1024, 256>>>(h_work, 4, NH1_, HID_, 1.f, 0.f, pdtH, 0,
                                         pz1 + (size_t)l*NH1_, 0, 2);
            // W2 grad partials (split 2), then fused W2 SGD + b2/b1 bias SGD
            gemmx(1,0, HID_, D_, NT_, 2, 1.f, pgl + (size_t)l*NH1_, HID_, pdh, D_, 0.f, 0, 0, 0);
            reduce_w2b<<<NB_W2 + (D_+HID_)/256, 256>>>(h_work, 2, pW2 + (size_t)l*HID_*D_,
                                                       pdh, pdtH, pb2 + l*D_, pb1 + l*HID_);
            // dtD(work) = dtH @ W1^T (pre-update W1), split 16 -> ln2 bwd accumulate
            gemmx(0,1, NT_, D_, HID_, 16, 1.f, pdtH, HID_, pW1 + (size_t)l*D_*HID_, HID_, 0.f, 0, 0, 0);
            ln_bwd_f<<<NT_, 256>>>(phmid + (size_t)l*ND_, h_work, 16, ln2s + l*D_, pdh, 1);
            // W1 -= LR * m^T @ dtH  (split 2 + reduce)
            gemmx(1,0, D_, HID_, NT_, 2, 1.f, pm + (size_t)l*ND_, D_, pdtH, HID_, 0.f, 0, 0, 0);
            reduce_k<<<(D_*HID_)/1024, 256>>>(h_work, 2, D_*HID_, HID_, -LR_, 1.f,
                                              pW1 + (size_t)l*D_*HID_, 0, 0, 0, 0);

            // dob(work) = dh @ Wo^T  (split 16; attn_bwd1 reduces inline)
            gemmx(0,1, NT_, D_, D_, 16, 1.f, pdh, D_, Wo + (size_t)l*D_*D_, D_, 0.f, 0, 0, 0);
            attn_bwd1<<<dim3(S_,NH_,B_), 256>>>(pqkv + (size_t)l*NQ_, patt + (size_t)l*NA_,
                                                h_work, 16, pdob, pds, pdqkv);
            attn_bwd2<<<dim3(S_,NH_,B_), 256>>>(pqkv + (size_t)l*NQ_, patt + (size_t)l*NA_,
                                                pdob, pds, pdqkv);
            // dtD(work) = dqkv @ Wqkv^T, split 8 -> ln1 bwd accumulate
            gemmx(0,1, NT_, D_, 3*D_, 8, 1.f, pdqkv, 3*D_, Wqkv + (size_t)l*D_*3*D_, 3*D_, 0.f, 0, 0, 0);
            ln_bwd_f<<<NT_, 256>>>(ph + (size_t)l*ND_, h_work, 8, ln1s + l*D_, pdh, 1);
        }
    }
    (void)in_sizes; (void)n_in; (void)out_size;
}